// round 4
// baseline (speedup 1.0000x reference)
#include <cuda_runtime.h>

// Problem constants
static constexpr int NB   = 4096;
static constexpr int CN   = 62;
static constexpr int FIN  = 256;
static constexpr int HID  = 64;
static constexpr int TOPK = 10;

static constexpr int NT   = 512;   // threads per CTA

// SMEM strides (floats)
static constexpr int XS_LD = 260;  // x tile stride (rows 4 banks apart, %4==0)
static constexpr int HB_LD = 68;   // all [64,64] buffers (16B-aligned rows, 4-bank skew)

// SMEM layout offsets (floats)
static constexpr int XS_OFF   = 0;                 // 64*260 = 16640 (x; adj overlays after phase 1)
static constexpr int ADJ_OFF  = 0;                 // 64*64 overlay
static constexpr int WB_OFF   = 16640;             // 4*4096 = 16384 weight staging
static constexpr int MASK_OFF = WB_OFF + 16384;    // 33024: 4352
static constexpr int HH_OFF   = MASK_OFF + 4352;   // 37376: 4352 (xa then h)
static constexpr int A_OFF    = HH_OFF + 4352;     // 41728: 4352 (xr / hr)
static constexpr int B_OFF    = A_OFF + 4352;      // 46080: 4352 (xroot / hroot)
static constexpr int TV_OFF   = B_OFF + 4352;      // 50432: 620 topk values
static constexpr int TI_OFF   = TV_OFF + 620;      // 51052: 620 topk indices (int)
static constexpr int SMEM_FLOATS = TI_OFF + 620;   // 51672 floats = 206688 B

__device__ __forceinline__ float4 fma4(float s, float4 a, float4 b) {
    b.x = fmaf(s, a.x, b.x); b.y = fmaf(s, a.y, b.y);
    b.z = fmaf(s, a.z, b.z); b.w = fmaf(s, a.w, b.w);
    return b;
}

__global__ __launch_bounds__(NT, 1) void residual_graph_kernel(
    const float* __restrict__ x,
    const float* __restrict__ gate_w,  const float* __restrict__ gate_b,
    const float* __restrict__ bnlin_w, const float* __restrict__ bnlin_b,
    const float* __restrict__ rel_w1,  const float* __restrict__ rel_b1,
    const float* __restrict__ root_w1,
    const float* __restrict__ rel_w_mid, const float* __restrict__ rel_b_mid,
    const float* __restrict__ root_w_mid,
    float* __restrict__ out)
{
    extern __shared__ float sm[];
    const int b    = blockIdx.x;
    const int tid  = threadIdx.x;
    const int lane = tid & 31;
    const int wid  = tid >> 5;

    // ---------------- Phase 0: load x tile into padded SMEM ----------------
    {
        const float4* xg  = reinterpret_cast<const float4*>(x + (size_t)b * (CN * FIN));
        float4*       xs4 = reinterpret_cast<float4*>(sm + XS_OFF);
        for (int i = tid; i < CN * 64; i += NT) {
            int r = i >> 6, q = i & 63;
            xs4[r * (XS_LD / 4) + q] = xg[i];
        }
        float4 z = make_float4(0.f, 0.f, 0.f, 0.f);
        if (tid < 2 * 64) {
            int r = 62 + (tid >> 6), q = tid & 63;
            xs4[r * (XS_LD / 4) + q] = z;
        }
    }
    __syncthreads();

    // ---- Phase 1: fused quad GEMM  [62,256] x [256,64] x 4 matrices -------
    // grp 0: gate_w -> x_mask (tanh+b), grp 1: bnlin_w -> xa (tanh+b),
    // grp 2: rel_w1 -> A (raw),         grp 3: root_w1 -> B (raw)
    {
        const int grp = tid >> 7;        // matrix id
        const int t7  = tid & 127;
        const int rg  = t7 >> 3;         // 0..15, rows rg+16i
        const int c0  = (t7 & 7) * 8;    // col base

        float acc[4][8];
        #pragma unroll
        for (int i = 0; i < 4; ++i)
            #pragma unroll
            for (int q = 0; q < 8; ++q) acc[i][q] = 0.f;

        for (int ch = 0; ch < 4; ++ch) {
            // stage 4 weight chunks [64,64] each
            {
                const float4* g0 = reinterpret_cast<const float4*>(gate_w)  + ch * 1024;
                const float4* g1 = reinterpret_cast<const float4*>(bnlin_w) + ch * 1024;
                const float4* g2 = reinterpret_cast<const float4*>(rel_w1)  + ch * 1024;
                const float4* g3 = reinterpret_cast<const float4*>(root_w1) + ch * 1024;
                float4* wb4 = reinterpret_cast<float4*>(sm + WB_OFF);
                for (int i = tid; i < 1024; i += NT) {
                    wb4[i]        = g0[i];
                    wb4[1024 + i] = g1[i];
                    wb4[2048 + i] = g2[i];
                    wb4[3072 + i] = g3[i];
                }
            }
            __syncthreads();

            const float* wm  = sm + WB_OFF + grp * 4096;
            const float* xsb = sm + XS_OFF + ch * 64;
            #pragma unroll 2
            for (int kk = 0; kk < 64; kk += 4) {
                float4 xq[4];
                #pragma unroll
                for (int i = 0; i < 4; ++i)
                    xq[i] = *reinterpret_cast<const float4*>(xsb + (rg + 16 * i) * XS_LD + kk);
                #pragma unroll
                for (int k = 0; k < 4; ++k) {
                    float4 wa = *reinterpret_cast<const float4*>(wm + (kk + k) * 64 + c0);
                    float4 wb = *reinterpret_cast<const float4*>(wm + (kk + k) * 64 + c0 + 4);
                    #pragma unroll
                    for (int i = 0; i < 4; ++i) {
                        float xs_ = (k == 0) ? xq[i].x : (k == 1) ? xq[i].y
                                  : (k == 2) ? xq[i].z : xq[i].w;
                        acc[i][0] = fmaf(xs_, wa.x, acc[i][0]);
                        acc[i][1] = fmaf(xs_, wa.y, acc[i][1]);
                        acc[i][2] = fmaf(xs_, wa.z, acc[i][2]);
                        acc[i][3] = fmaf(xs_, wa.w, acc[i][3]);
                        acc[i][4] = fmaf(xs_, wb.x, acc[i][4]);
                        acc[i][5] = fmaf(xs_, wb.y, acc[i][5]);
                        acc[i][6] = fmaf(xs_, wb.z, acc[i][6]);
                        acc[i][7] = fmaf(xs_, wb.w, acc[i][7]);
                    }
                }
            }
            __syncthreads();
        }

        // epilogue
        if (grp < 2) {
            const float* bv = grp ? bnlin_b : gate_b;
            float bb[8];
            #pragma unroll
            for (int q = 0; q < 8; ++q) bb[q] = __ldg(&bv[c0 + q]);
            float* base = sm + (grp ? HH_OFF : MASK_OFF);
            #pragma unroll
            for (int i = 0; i < 4; ++i) {
                int r = rg + 16 * i;
                float* dst = base + r * HB_LD + c0;
                #pragma unroll
                for (int q = 0; q < 8; ++q) dst[q] = tanhf(acc[i][q] + bb[q]);
            }
        } else {
            float* base = sm + (grp == 2 ? A_OFF : B_OFF);
            #pragma unroll
            for (int i = 0; i < 4; ++i) {
                int r = rg + 16 * i;
                float* dst = base + r * HB_LD + c0;
                #pragma unroll
                for (int q = 0; q < 8; ++q) dst[q] = acc[i][q];
            }
        }
    }
    __syncthreads();

    // -------- Phase 2: adjacency logits adj[r][j] = <xa[r], xa[j]> ---------
    // rows 62,63 of xa hold garbage from tanh epilogue? No: epilogue wrote all
    // rows 0..63; rows 62,63 are tanh(garbage) but we never read them (r<CN,
    // j<CN guards below). xa rows 62/63 ARE read as aj only when jg*8+q >= CN,
    // and those products are discarded by the j<CN store guard.
    {
        const int rr = tid >> 3;      // row 0..63
        const int jg = tid & 7;       // col group
        float s8[8];
        #pragma unroll
        for (int q = 0; q < 8; ++q) s8[q] = 0.f;
        const float* xa = sm + HH_OFF;
        for (int k = 0; k < HID; k += 4) {
            float4 a = *reinterpret_cast<const float4*>(xa + rr * HB_LD + k);
            #pragma unroll
            for (int q = 0; q < 8; ++q) {
                float4 aj = *reinterpret_cast<const float4*>(xa + (jg * 8 + q) * HB_LD + k);
                s8[q] = fmaf(a.x, aj.x, s8[q]);
                s8[q] = fmaf(a.y, aj.y, s8[q]);
                s8[q] = fmaf(a.z, aj.z, s8[q]);
                s8[q] = fmaf(a.w, aj.w, s8[q]);
            }
        }
        float* adj = sm + ADJ_OFF;
        if (rr < CN) {
            #pragma unroll
            for (int q = 0; q < 8; ++q) {
                int j = jg * 8 + q;
                if (j < CN) adj[rr * 64 + j] = s8[q];
            }
        }
    }
    __syncthreads();

    // ---------- Phase 3: softmax per row + top-10 selection ----------------
    {
        int* tix = reinterpret_cast<int*>(sm);
        for (int r = wid; r < CN; r += 16) {
            const float* arow = sm + ADJ_OFF + r * 64;
            float a0 = arow[lane];
            bool ok1 = (lane + 32) < CN;
            float a1 = ok1 ? arow[lane + 32] : -1e30f;
            float mx = fmaxf(a0, a1);
            #pragma unroll
            for (int o = 16; o; o >>= 1) mx = fmaxf(mx, __shfl_xor_sync(0xffffffffu, mx, o));
            float e0 = expf(a0 - mx);
            float e1 = ok1 ? expf(a1 - mx) : 0.f;
            float s = e0 + e1;
            #pragma unroll
            for (int o = 16; o; o >>= 1) s += __shfl_xor_sync(0xffffffffu, s, o);
            float inv = 1.f / s;
            float p0 = e0 * inv;
            float p1 = e1 * inv;
            float v0 = p0;
            float v1 = ok1 ? p1 : -1.f;
            for (int m = 0; m < TOPK; ++m) {
                float c  = fmaxf(v0, v1);
                float cm = c;
                #pragma unroll
                for (int o = 16; o; o >>= 1) cm = fmaxf(cm, __shfl_xor_sync(0xffffffffu, cm, o));
                unsigned ball = __ballot_sync(0xffffffffu, c == cm);
                int owner = __ffs(ball) - 1;
                if (lane == owner) {
                    if (v0 == cm) {
                        sm[TV_OFF + r * TOPK + m] = p0;
                        tix[TI_OFF + r * TOPK + m] = lane;
                        v0 = -1.f;
                    } else {
                        sm[TV_OFF + r * TOPK + m] = p1;
                        tix[TI_OFF + r * TOPK + m] = lane + 32;
                        v1 = -1.f;
                    }
                }
            }
        }
    }
    __syncthreads();

    // ---------- Phase 4: h1 = relu(adjS @ A + rel_b1 + B) ------------------
    {
        const int r  = tid >> 3;
        const int cc = (tid & 7) * 8;
        float* hrow = sm + HH_OFF + r * HB_LD + cc;
        if (r < CN) {
            const int* tix = reinterpret_cast<const int*>(sm);
            float4 s0 = make_float4(0.f, 0.f, 0.f, 0.f);
            float4 s1 = make_float4(0.f, 0.f, 0.f, 0.f);
            #pragma unroll
            for (int m = 0; m < TOPK; ++m) {
                int   j = tix[TI_OFF + r * TOPK + m];
                float v = sm[TV_OFF + r * TOPK + m];
                const float4* src = reinterpret_cast<const float4*>(sm + A_OFF + j * HB_LD + cc);
                s0 = fma4(v, src[0], s0);
                s1 = fma4(v, src[1], s1);
            }
            const float* rt = sm + B_OFF + r * HB_LD + cc;
            hrow[0] = fmaxf(s0.x + __ldg(&rel_b1[cc + 0]) + rt[0], 0.f);
            hrow[1] = fmaxf(s0.y + __ldg(&rel_b1[cc + 1]) + rt[1], 0.f);
            hrow[2] = fmaxf(s0.z + __ldg(&rel_b1[cc + 2]) + rt[2], 0.f);
            hrow[3] = fmaxf(s0.w + __ldg(&rel_b1[cc + 3]) + rt[3], 0.f);
            hrow[4] = fmaxf(s1.x + __ldg(&rel_b1[cc + 4]) + rt[4], 0.f);
            hrow[5] = fmaxf(s1.y + __ldg(&rel_b1[cc + 5]) + rt[5], 0.f);
            hrow[6] = fmaxf(s1.z + __ldg(&rel_b1[cc + 6]) + rt[6], 0.f);
            hrow[7] = fmaxf(s1.w + __ldg(&rel_b1[cc + 7]) + rt[7], 0.f);
        } else {
            #pragma unroll
            for (int q = 0; q < 8; ++q) hrow[q] = 0.f;
        }
    }
    __syncthreads();

    // ---------------- Phase 5: six graph-conv layers -----------------------
    for (int L = 0; L < 6; ++L) {
        // stage mid weights [64,64] x 2
        {
            const float4* g0 = reinterpret_cast<const float4*>(rel_w_mid)  + L * 1024;
            const float4* g1 = reinterpret_cast<const float4*>(root_w_mid) + L * 1024;
            float4* wb4 = reinterpret_cast<float4*>(sm + WB_OFF);
            for (int i = tid; i < 1024; i += NT) {
                wb4[i]        = g0[i];
                wb4[1024 + i] = g1[i];
            }
        }
        __syncthreads();

        // hr = h @ rel_w (mtx 0 -> A), hroot = h @ root_w (mtx 1 -> B)
        {
            const int mtx = tid >> 8;
            const int t8  = tid & 255;
            const int rg  = t8 >> 3;        // rows rg, rg+32
            const int c0  = (t8 & 7) * 8;

            float acc[2][8];
            #pragma unroll
            for (int i = 0; i < 2; ++i)
                #pragma unroll
                for (int q = 0; q < 8; ++q) acc[i][q] = 0.f;

            const float* wm = sm + WB_OFF + mtx * 4096;
            const float* hb = sm + HH_OFF;
            #pragma unroll 2
            for (int kk = 0; kk < HID; kk += 4) {
                float4 hq[2];
                hq[0] = *reinterpret_cast<const float4*>(hb + rg * HB_LD + kk);
                hq[1] = *reinterpret_cast<const float4*>(hb + (rg + 32) * HB_LD + kk);
                #pragma unroll
                for (int k = 0; k < 4; ++k) {
                    float4 wa = *reinterpret_cast<const float4*>(wm + (kk + k) * 64 + c0);
                    float4 wb = *reinterpret_cast<const float4*>(wm + (kk + k) * 64 + c0 + 4);
                    #pragma unroll
                    for (int i = 0; i < 2; ++i) {
                        float hs = (k == 0) ? hq[i].x : (k == 1) ? hq[i].y
                                 : (k == 2) ? hq[i].z : hq[i].w;
                        acc[i][0] = fmaf(hs, wa.x, acc[i][0]);
                        acc[i][1] = fmaf(hs, wa.y, acc[i][1]);
                        acc[i][2] = fmaf(hs, wa.z, acc[i][2]);
                        acc[i][3] = fmaf(hs, wa.w, acc[i][3]);
                        acc[i][4] = fmaf(hs, wb.x, acc[i][4]);
                        acc[i][5] = fmaf(hs, wb.y, acc[i][5]);
                        acc[i][6] = fmaf(hs, wb.z, acc[i][6]);
                        acc[i][7] = fmaf(hs, wb.w, acc[i][7]);
                    }
                }
            }
            float* base = sm + (mtx ? B_OFF : A_OFF);
            #pragma unroll
            for (int i = 0; i < 2; ++i) {
                int r = rg + 32 * i;
                float* dst = base + r * HB_LD + c0;
                #pragma unroll
                for (int q = 0; q < 8; ++q) dst[q] = acc[i][q];
            }
        }
        __syncthreads();

        // h update: t = relu(adjS @ hr + rel_b_mid[L] + hroot)
        // L<5: h += t; L==5: out = t * mask (fused output)
        {
            const int r  = tid >> 3;
            const int cc = (tid & 7) * 8;
            if (r < CN) {
                const int* tix = reinterpret_cast<const int*>(sm);
                const float* relb = rel_b_mid + L * 64;
                float4 s0 = make_float4(0.f, 0.f, 0.f, 0.f);
                float4 s1 = make_float4(0.f, 0.f, 0.f, 0.f);
                #pragma unroll
                for (int m = 0; m < TOPK; ++m) {
                    int   j = tix[TI_OFF + r * TOPK + m];
                    float v = sm[TV_OFF + r * TOPK + m];
                    const float4* src = reinterpret_cast<const float4*>(sm + A_OFF + j * HB_LD + cc);
                    s0 = fma4(v, src[0], s0);
                    s1 = fma4(v, src[1], s1);
                }
                const float* rt = sm + B_OFF + r * HB_LD + cc;
                float* hrow = sm + HH_OFF + r * HB_LD + cc;
                float t[8];
                t[0] = fmaxf(s0.x + __ldg(&relb[cc + 0]) + rt[0], 0.f);
                t[1] = fmaxf(s0.y + __ldg(&relb[cc + 1]) + rt[1], 0.f);
                t[2] = fmaxf(s0.z + __ldg(&relb[cc + 2]) + rt[2], 0.f);
                t[3] = fmaxf(s0.w + __ldg(&relb[cc + 3]) + rt[3], 0.f);
                t[4] = fmaxf(s1.x + __ldg(&relb[cc + 4]) + rt[4], 0.f);
                t[5] = fmaxf(s1.y + __ldg(&relb[cc + 5]) + rt[5], 0.f);
                t[6] = fmaxf(s1.z + __ldg(&relb[cc + 6]) + rt[6], 0.f);
                t[7] = fmaxf(s1.w + __ldg(&relb[cc + 7]) + rt[7], 0.f);
                if (L < 5) {
                    #pragma unroll
                    for (int q = 0; q < 8; ++q) hrow[q] += t[q];
                } else {
                    const float* mrow = sm + MASK_OFF + r * HB_LD + cc;
                    float4 o0, o1;
                    o0.x = t[0] * mrow[0]; o0.y = t[1] * mrow[1];
                    o0.z = t[2] * mrow[2]; o0.w = t[3] * mrow[3];
                    o1.x = t[4] * mrow[4]; o1.y = t[5] * mrow[5];
                    o1.z = t[6] * mrow[6]; o1.w = t[7] * mrow[7];
                    float4* og = reinterpret_cast<float4*>(out + (size_t)b * (CN * HID) + r * HID + cc);
                    og[0] = o0;
                    og[1] = o1;
                }
            }
        }
        if (L < 5) __syncthreads();
    }
}

extern "C" void kernel_launch(void* const* d_in, const int* in_sizes, int n_in,
                              void* d_out, int out_size) {
    const float* x          = (const float*)d_in[0];
    const float* gate_w     = (const float*)d_in[1];
    const float* gate_b     = (const float*)d_in[2];
    const float* bnlin_w    = (const float*)d_in[3];
    const float* bnlin_b    = (const float*)d_in[4];
    const float* rel_w1     = (const float*)d_in[5];
    const float* rel_b1     = (const float*)d_in[6];
    const float* root_w1    = (const float*)d_in[7];
    const float* rel_w_mid  = (const float*)d_in[8];
    const float* rel_b_mid  = (const float*)d_in[9];
    const float* root_w_mid = (const float*)d_in[10];
    float* out = (float*)d_out;

    (void)in_sizes; (void)n_in; (void)out_size;

    const int smem_bytes = SMEM_FLOATS * 4;
    cudaFuncSetAttribute(residual_graph_kernel,
                         cudaFuncAttributeMaxDynamicSharedMemorySize, smem_bytes);
    residual_graph_kernel<<<NB, NT, smem_bytes>>>(
        x, gate_w, gate_b, bnlin_w, bnlin_b, rel_w1, rel_b1, root_w1,
        rel_w_mid, rel_b_mid, root_w_mid, out);
}

// round 5
// speedup vs baseline: 1.7802x; 1.7802x over previous
#include <cuda_runtime.h>

// Problem constants
static constexpr int NB   = 4096;
static constexpr int CN   = 62;
static constexpr int FIN  = 256;
static constexpr int HID  = 64;
static constexpr int TOPK = 10;

static constexpr int NT   = 512;   // threads per CTA

// SMEM strides (floats)
static constexpr int XS_LD = 260;  // x tile stride
static constexpr int HB_LD = 68;   // all [64,64] buffers (16B rows, stride%32=4 -> 8-consecutive-row float4 reads conflict-free)

// SMEM layout offsets (floats)
static constexpr int XS_OFF   = 0;                 // 64*260 = 16640 (x; adj overlays after phase 1)
static constexpr int ADJ_OFF  = 0;                 // 64*64 overlay
static constexpr int WB_OFF   = 16640;             // 4*4096 = 16384 weight staging
static constexpr int MASK_OFF = WB_OFF + 16384;    // 33024: 4352
static constexpr int HH_OFF   = MASK_OFF + 4352;   // 37376: 4352 (xa then h)
static constexpr int A_OFF    = HH_OFF + 4352;     // 41728: 4352 (xr / hr)
static constexpr int B_OFF    = A_OFF + 4352;      // 46080: 4352 (xroot / hroot)
static constexpr int TV_OFF   = B_OFF + 4352;      // 50432: 620 topk values
static constexpr int TI_OFF   = TV_OFF + 620;      // 51052: 620 topk indices (int)
static constexpr int SMEM_FLOATS = TI_OFF + 620;   // 51672 floats = 206688 B

__device__ __forceinline__ float4 fma4(float s, float4 a, float4 b) {
    b.x = fmaf(s, a.x, b.x); b.y = fmaf(s, a.y, b.y);
    b.z = fmaf(s, a.z, b.z); b.w = fmaf(s, a.w, b.w);
    return b;
}

__global__ __launch_bounds__(NT, 1) void residual_graph_kernel(
    const float* __restrict__ x,
    const float* __restrict__ gate_w,  const float* __restrict__ gate_b,
    const float* __restrict__ bnlin_w, const float* __restrict__ bnlin_b,
    const float* __restrict__ rel_w1,  const float* __restrict__ rel_b1,
    const float* __restrict__ root_w1,
    const float* __restrict__ rel_w_mid, const float* __restrict__ rel_b_mid,
    const float* __restrict__ root_w_mid,
    float* __restrict__ out)
{
    extern __shared__ float sm[];
    const int b    = blockIdx.x;
    const int tid  = threadIdx.x;
    const int lane = tid & 31;
    const int wid  = tid >> 5;

    // ---------------- Phase 0: load x tile into padded SMEM ----------------
    {
        const float4* xg  = reinterpret_cast<const float4*>(x + (size_t)b * (CN * FIN));
        float4*       xs4 = reinterpret_cast<float4*>(sm + XS_OFF);
        for (int i = tid; i < CN * 64; i += NT) {
            int r = i >> 6, q = i & 63;
            xs4[r * (XS_LD / 4) + q] = xg[i];
        }
        float4 z = make_float4(0.f, 0.f, 0.f, 0.f);
        if (tid < 2 * 64) {
            int r = 62 + (tid >> 6), q = tid & 63;
            xs4[r * (XS_LD / 4) + q] = z;
        }
    }
    __syncthreads();

    // ---- Phase 1: fused quad GEMM  [62,256] x [256,64] x 4 matrices -------
    // grp 0: gate_w -> x_mask (tanh+b), grp 1: bnlin_w -> xa (tanh+b),
    // grp 2: rel_w1 -> A (raw),         grp 3: root_w1 -> B (raw)
    // Column split per thread: cols [cg*4, cg*4+3] and [32+cg*4, 32+cg*4+3]
    // so each 8-lane LDS phase of a weight load covers contiguous 128B.
    {
        const int grp = tid >> 7;        // matrix id
        const int t7  = tid & 127;
        const int rg  = t7 >> 3;         // 0..15, rows rg+16*i
        const int cg  = t7 & 7;
        const int c0a = cg * 4;
        const int c0b = 32 + cg * 4;

        float4 acc0[4], acc1[4];
        #pragma unroll
        for (int i = 0; i < 4; ++i) {
            acc0[i] = make_float4(0.f, 0.f, 0.f, 0.f);
            acc1[i] = make_float4(0.f, 0.f, 0.f, 0.f);
        }

        for (int ch = 0; ch < 4; ++ch) {
            {
                const float4* g0 = reinterpret_cast<const float4*>(gate_w)  + ch * 1024;
                const float4* g1 = reinterpret_cast<const float4*>(bnlin_w) + ch * 1024;
                const float4* g2 = reinterpret_cast<const float4*>(rel_w1)  + ch * 1024;
                const float4* g3 = reinterpret_cast<const float4*>(root_w1) + ch * 1024;
                float4* wb4 = reinterpret_cast<float4*>(sm + WB_OFF);
                for (int i = tid; i < 1024; i += NT) {
                    wb4[i]        = g0[i];
                    wb4[1024 + i] = g1[i];
                    wb4[2048 + i] = g2[i];
                    wb4[3072 + i] = g3[i];
                }
            }
            __syncthreads();

            const float* wm  = sm + WB_OFF + grp * 4096;
            const float* xsb = sm + XS_OFF + ch * 64;
            #pragma unroll 2
            for (int kk = 0; kk < 64; kk += 4) {
                float4 xq[4];
                #pragma unroll
                for (int i = 0; i < 4; ++i)
                    xq[i] = *reinterpret_cast<const float4*>(xsb + (rg + 16 * i) * XS_LD + kk);
                #pragma unroll
                for (int k = 0; k < 4; ++k) {
                    float4 wa = *reinterpret_cast<const float4*>(wm + (kk + k) * 64 + c0a);
                    float4 wb = *reinterpret_cast<const float4*>(wm + (kk + k) * 64 + c0b);
                    #pragma unroll
                    for (int i = 0; i < 4; ++i) {
                        float xs_ = (k == 0) ? xq[i].x : (k == 1) ? xq[i].y
                                  : (k == 2) ? xq[i].z : xq[i].w;
                        acc0[i] = fma4(xs_, wa, acc0[i]);
                        acc1[i] = fma4(xs_, wb, acc1[i]);
                    }
                }
            }
            __syncthreads();
        }

        // epilogue
        if (grp < 2) {
            const float* bv = grp ? bnlin_b : gate_b;
            float4 ba, bb;
            ba.x = __ldg(&bv[c0a + 0]); ba.y = __ldg(&bv[c0a + 1]);
            ba.z = __ldg(&bv[c0a + 2]); ba.w = __ldg(&bv[c0a + 3]);
            bb.x = __ldg(&bv[c0b + 0]); bb.y = __ldg(&bv[c0b + 1]);
            bb.z = __ldg(&bv[c0b + 2]); bb.w = __ldg(&bv[c0b + 3]);
            float* base = sm + (grp ? HH_OFF : MASK_OFF);
            #pragma unroll
            for (int i = 0; i < 4; ++i) {
                int r = rg + 16 * i;
                float4 ta, tb;
                ta.x = tanhf(acc0[i].x + ba.x); ta.y = tanhf(acc0[i].y + ba.y);
                ta.z = tanhf(acc0[i].z + ba.z); ta.w = tanhf(acc0[i].w + ba.w);
                tb.x = tanhf(acc1[i].x + bb.x); tb.y = tanhf(acc1[i].y + bb.y);
                tb.z = tanhf(acc1[i].z + bb.z); tb.w = tanhf(acc1[i].w + bb.w);
                *reinterpret_cast<float4*>(base + r * HB_LD + c0a) = ta;
                *reinterpret_cast<float4*>(base + r * HB_LD + c0b) = tb;
            }
        } else {
            float* base = sm + (grp == 2 ? A_OFF : B_OFF);
            #pragma unroll
            for (int i = 0; i < 4; ++i) {
                int r = rg + 16 * i;
                *reinterpret_cast<float4*>(base + r * HB_LD + c0a) = acc0[i];
                *reinterpret_cast<float4*>(base + r * HB_LD + c0b) = acc1[i];
            }
        }
    }
    __syncthreads();

    // -------- Phase 2: adjacency logits adj[r][j] = <xa[r], xa[j]> ---------
    // Thread covers cols j = jg + 8q (q=0..7): an 8-lane LDS phase reads 8
    // CONSECUTIVE rows (stride 68 = 4 mod 32 banks) -> conflict-free.
    {
        const int rr = tid >> 3;      // row 0..63
        const int jg = tid & 7;
        float s8[8];
        #pragma unroll
        for (int q = 0; q < 8; ++q) s8[q] = 0.f;
        const float* xa = sm + HH_OFF;
        for (int k = 0; k < HID; k += 4) {
            float4 a = *reinterpret_cast<const float4*>(xa + rr * HB_LD + k);
            #pragma unroll
            for (int q = 0; q < 8; ++q) {
                float4 aj = *reinterpret_cast<const float4*>(xa + (jg + 8 * q) * HB_LD + k);
                s8[q] = fmaf(a.x, aj.x, s8[q]);
                s8[q] = fmaf(a.y, aj.y, s8[q]);
                s8[q] = fmaf(a.z, aj.z, s8[q]);
                s8[q] = fmaf(a.w, aj.w, s8[q]);
            }
        }
        float* adj = sm + ADJ_OFF;
        if (rr < CN) {
            #pragma unroll
            for (int q = 0; q < 8; ++q) {
                int j = jg + 8 * q;
                if (j < CN) adj[rr * 64 + j] = s8[q];
            }
        }
    }
    __syncthreads();

    // ---------- Phase 3: softmax per row + top-10 selection ----------------
    {
        int* tix = reinterpret_cast<int*>(sm);
        for (int r = wid; r < CN; r += 16) {
            const float* arow = sm + ADJ_OFF + r * 64;
            float a0 = arow[lane];
            bool ok1 = (lane + 32) < CN;
            float a1 = ok1 ? arow[lane + 32] : -1e30f;
            float mx = fmaxf(a0, a1);
            #pragma unroll
            for (int o = 16; o; o >>= 1) mx = fmaxf(mx, __shfl_xor_sync(0xffffffffu, mx, o));
            float e0 = expf(a0 - mx);
            float e1 = ok1 ? expf(a1 - mx) : 0.f;
            float s = e0 + e1;
            #pragma unroll
            for (int o = 16; o; o >>= 1) s += __shfl_xor_sync(0xffffffffu, s, o);
            float inv = 1.f / s;
            float p0 = e0 * inv;
            float p1 = e1 * inv;
            float v0 = p0;
            float v1 = ok1 ? p1 : -1.f;
            for (int m = 0; m < TOPK; ++m) {
                float c  = fmaxf(v0, v1);
                float cm = c;
                #pragma unroll
                for (int o = 16; o; o >>= 1) cm = fmaxf(cm, __shfl_xor_sync(0xffffffffu, cm, o));
                unsigned ball = __ballot_sync(0xffffffffu, c == cm);
                int owner = __ffs(ball) - 1;
                if (lane == owner) {
                    if (v0 == cm) {
                        sm[TV_OFF + r * TOPK + m] = p0;
                        tix[TI_OFF + r * TOPK + m] = lane;
                        v0 = -1.f;
                    } else {
                        sm[TV_OFF + r * TOPK + m] = p1;
                        tix[TI_OFF + r * TOPK + m] = lane + 32;
                        v1 = -1.f;
                    }
                }
            }
        }
    }
    __syncthreads();

    // ---------- Phase 4: h1 = relu(adjS @ A + rel_b1 + B) ------------------
    // Column split cg*4 / 32+cg*4 -> all smem accesses contiguous per phase.
    {
        const int r   = tid >> 3;
        const int cg  = tid & 7;
        const int c0a = cg * 4;
        const int c0b = 32 + cg * 4;
        float* hr0 = sm + HH_OFF + r * HB_LD + c0a;
        float* hr1 = sm + HH_OFF + r * HB_LD + c0b;
        if (r < CN) {
            const int* tix = reinterpret_cast<const int*>(sm);
            float4 s0 = make_float4(0.f, 0.f, 0.f, 0.f);
            float4 s1 = make_float4(0.f, 0.f, 0.f, 0.f);
            #pragma unroll
            for (int m = 0; m < TOPK; ++m) {
                int   j = tix[TI_OFF + r * TOPK + m];
                float v = sm[TV_OFF + r * TOPK + m];
                float4 pa = *reinterpret_cast<const float4*>(sm + A_OFF + j * HB_LD + c0a);
                float4 pb = *reinterpret_cast<const float4*>(sm + A_OFF + j * HB_LD + c0b);
                s0 = fma4(v, pa, s0);
                s1 = fma4(v, pb, s1);
            }
            float4 r0 = *reinterpret_cast<const float4*>(sm + B_OFF + r * HB_LD + c0a);
            float4 r1 = *reinterpret_cast<const float4*>(sm + B_OFF + r * HB_LD + c0b);
            float4 t0, t1;
            t0.x = fmaxf(s0.x + __ldg(&rel_b1[c0a + 0]) + r0.x, 0.f);
            t0.y = fmaxf(s0.y + __ldg(&rel_b1[c0a + 1]) + r0.y, 0.f);
            t0.z = fmaxf(s0.z + __ldg(&rel_b1[c0a + 2]) + r0.z, 0.f);
            t0.w = fmaxf(s0.w + __ldg(&rel_b1[c0a + 3]) + r0.w, 0.f);
            t1.x = fmaxf(s1.x + __ldg(&rel_b1[c0b + 0]) + r1.x, 0.f);
            t1.y = fmaxf(s1.y + __ldg(&rel_b1[c0b + 1]) + r1.y, 0.f);
            t1.z = fmaxf(s1.z + __ldg(&rel_b1[c0b + 2]) + r1.z, 0.f);
            t1.w = fmaxf(s1.w + __ldg(&rel_b1[c0b + 3]) + r1.w, 0.f);
            *reinterpret_cast<float4*>(hr0) = t0;
            *reinterpret_cast<float4*>(hr1) = t1;
        } else {
            float4 z = make_float4(0.f, 0.f, 0.f, 0.f);
            *reinterpret_cast<float4*>(hr0) = z;
            *reinterpret_cast<float4*>(hr1) = z;
        }
    }
    __syncthreads();

    // ---------------- Phase 5: six graph-conv layers -----------------------
    for (int L = 0; L < 6; ++L) {
        // stage mid weights [64,64] x 2
        {
            const float4* g0 = reinterpret_cast<const float4*>(rel_w_mid)  + L * 1024;
            const float4* g1 = reinterpret_cast<const float4*>(root_w_mid) + L * 1024;
            float4* wb4 = reinterpret_cast<float4*>(sm + WB_OFF);
            for (int i = tid; i < 1024; i += NT) {
                wb4[i]        = g0[i];
                wb4[1024 + i] = g1[i];
            }
        }
        __syncthreads();

        // hr = h @ rel_w (mtx 0 -> A), hroot = h @ root_w (mtx 1 -> B)
        {
            const int mtx = tid >> 8;
            const int t8  = tid & 255;
            const int rg  = t8 >> 3;        // rows rg, rg+32
            const int cg  = t8 & 7;
            const int c0a = cg * 4;
            const int c0b = 32 + cg * 4;

            float4 acc0[2], acc1[2];
            #pragma unroll
            for (int i = 0; i < 2; ++i) {
                acc0[i] = make_float4(0.f, 0.f, 0.f, 0.f);
                acc1[i] = make_float4(0.f, 0.f, 0.f, 0.f);
            }

            const float* wm = sm + WB_OFF + mtx * 4096;
            const float* hb = sm + HH_OFF;
            #pragma unroll 2
            for (int kk = 0; kk < HID; kk += 4) {
                float4 hq[2];
                hq[0] = *reinterpret_cast<const float4*>(hb + rg * HB_LD + kk);
                hq[1] = *reinterpret_cast<const float4*>(hb + (rg + 32) * HB_LD + kk);
                #pragma unroll
                for (int k = 0; k < 4; ++k) {
                    float4 wa = *reinterpret_cast<const float4*>(wm + (kk + k) * 64 + c0a);
                    float4 wb = *reinterpret_cast<const float4*>(wm + (kk + k) * 64 + c0b);
                    #pragma unroll
                    for (int i = 0; i < 2; ++i) {
                        float hs = (k == 0) ? hq[i].x : (k == 1) ? hq[i].y
                                 : (k == 2) ? hq[i].z : hq[i].w;
                        acc0[i] = fma4(hs, wa, acc0[i]);
                        acc1[i] = fma4(hs, wb, acc1[i]);
                    }
                }
            }
            float* base = sm + (mtx ? B_OFF : A_OFF);
            #pragma unroll
            for (int i = 0; i < 2; ++i) {
                int r = rg + 32 * i;
                *reinterpret_cast<float4*>(base + r * HB_LD + c0a) = acc0[i];
                *reinterpret_cast<float4*>(base + r * HB_LD + c0b) = acc1[i];
            }
        }
        __syncthreads();

        // h update: t = relu(adjS @ hr + rel_b_mid[L] + hroot)
        // L<5: h += t; L==5: out = t * mask (fused output)
        {
            const int r   = tid >> 3;
            const int cg  = tid & 7;
            const int c0a = cg * 4;
            const int c0b = 32 + cg * 4;
            if (r < CN) {
                const int* tix = reinterpret_cast<const int*>(sm);
                const float* relb = rel_b_mid + L * 64;
                float4 s0 = make_float4(0.f, 0.f, 0.f, 0.f);
                float4 s1 = make_float4(0.f, 0.f, 0.f, 0.f);
                #pragma unroll
                for (int m = 0; m < TOPK; ++m) {
                    int   j = tix[TI_OFF + r * TOPK + m];
                    float v = sm[TV_OFF + r * TOPK + m];
                    float4 pa = *reinterpret_cast<const float4*>(sm + A_OFF + j * HB_LD + c0a);
                    float4 pb = *reinterpret_cast<const float4*>(sm + A_OFF + j * HB_LD + c0b);
                    s0 = fma4(v, pa, s0);
                    s1 = fma4(v, pb, s1);
                }
                float4 r0 = *reinterpret_cast<const float4*>(sm + B_OFF + r * HB_LD + c0a);
                float4 r1 = *reinterpret_cast<const float4*>(sm + B_OFF + r * HB_LD + c0b);
                float4 t0, t1;
                t0.x = fmaxf(s0.x + __ldg(&relb[c0a + 0]) + r0.x, 0.f);
                t0.y = fmaxf(s0.y + __ldg(&relb[c0a + 1]) + r0.y, 0.f);
                t0.z = fmaxf(s0.z + __ldg(&relb[c0a + 2]) + r0.z, 0.f);
                t0.w = fmaxf(s0.w + __ldg(&relb[c0a + 3]) + r0.w, 0.f);
                t1.x = fmaxf(s1.x + __ldg(&relb[c0b + 0]) + r1.x, 0.f);
                t1.y = fmaxf(s1.y + __ldg(&relb[c0b + 1]) + r1.y, 0.f);
                t1.z = fmaxf(s1.z + __ldg(&relb[c0b + 2]) + r1.z, 0.f);
                t1.w = fmaxf(s1.w + __ldg(&relb[c0b + 3]) + r1.w, 0.f);
                float* h0 = sm + HH_OFF + r * HB_LD + c0a;
                float* h1 = sm + HH_OFF + r * HB_LD + c0b;
                if (L < 5) {
                    float4 ha = *reinterpret_cast<const float4*>(h0);
                    float4 hbv = *reinterpret_cast<const float4*>(h1);
                    ha.x += t0.x; ha.y += t0.y; ha.z += t0.z; ha.w += t0.w;
                    hbv.x += t1.x; hbv.y += t1.y; hbv.z += t1.z; hbv.w += t1.w;
                    *reinterpret_cast<float4*>(h0) = ha;
                    *reinterpret_cast<float4*>(h1) = hbv;
                } else {
                    float4 m0 = *reinterpret_cast<const float4*>(sm + MASK_OFF + r * HB_LD + c0a);
                    float4 m1 = *reinterpret_cast<const float4*>(sm + MASK_OFF + r * HB_LD + c0b);
                    float4 o0, o1;
                    o0.x = t0.x * m0.x; o0.y = t0.y * m0.y; o0.z = t0.z * m0.z; o0.w = t0.w * m0.w;
                    o1.x = t1.x * m1.x; o1.y = t1.y * m1.y; o1.z = t1.z * m1.z; o1.w = t1.w * m1.w;
                    float* og = out + (size_t)b * (CN * HID) + r * HID;
                    *reinterpret_cast<float4*>(og + c0a) = o0;
                    *reinterpret_cast<float4*>(og + c0b) = o1;
                }
            }
        }
        if (L < 5) __syncthreads();
    }
}

extern "C" void kernel_launch(void* const* d_in, const int* in_sizes, int n_in,
                              void* d_out, int out_size) {
    const float* x          = (const float*)d_in[0];
    const float* gate_w     = (const float*)d_in[1];
    const float* gate_b     = (const float*)d_in[2];
    const float* bnlin_w    = (const float*)d_in[3];
    const float* bnlin_b    = (const float*)d_in[4];
    const float* rel_w1     = (const float*)d_in[5];
    const float* rel_b1     = (const float*)d_in[6];
    const float* root_w1    = (const float*)d_in[7];
    const float* rel_w_mid  = (const float*)d_in[8];
    const float* rel_b_mid  = (const float*)d_in[9];
    const float* root_w_mid = (const float*)d_in[10];
    float* out = (float*)d_out;

    (void)in_sizes; (void)n_in; (void)out_size;

    const int smem_bytes = SMEM_FLOATS * 4;
    cudaFuncSetAttribute(residual_graph_kernel,
                         cudaFuncAttributeMaxDynamicSharedMemorySize, smem_bytes);
    residual_graph_kernel<<<NB, NT, smem_bytes>>>(
        x, gate_w, gate_b, bnlin_w, bnlin_b, rel_w1, rel_b1, root_w1,
        rel_w_mid, rel_b_mid, root_w_mid, out);
}

// round 6
// speedup vs baseline: 1.8445x; 1.0361x over previous
#include <cuda_runtime.h>

// Problem constants
static constexpr int NB   = 4096;
static constexpr int CN   = 62;
static constexpr int FIN  = 256;
static constexpr int HID  = 64;
static constexpr int TOPK = 10;

static constexpr int NT   = 512;   // threads per CTA

// SMEM strides (floats)
static constexpr int XS_LD = 260;  // x tile stride
static constexpr int HB_LD = 68;   // all [64,64] buffers (16B rows, stride%32=4)

// SMEM layout offsets (floats)
static constexpr int XS_OFF   = 0;                 // 64*260 = 16640 (x; adj overlays after phase 1)
static constexpr int ADJ_OFF  = 0;                 // 64*64 overlay
static constexpr int WB_OFF   = 16640;             // 4*4096 = 16384 weight staging
static constexpr int MASK_OFF = WB_OFF + 16384;    // 33024: 4352
static constexpr int HH_OFF   = MASK_OFF + 4352;   // 37376: 4352 (xa then h)
static constexpr int A_OFF    = HH_OFF + 4352;     // 41728: 4352 (xr / hr)
static constexpr int B_OFF    = A_OFF + 4352;      // 46080: 4352 (xroot / hroot)
static constexpr int TV_OFF   = B_OFF + 4352;      // 50432: 620 topk values
static constexpr int TI_OFF   = TV_OFF + 620;      // 51052: 620 topk indices (int)
static constexpr int SMEM_FLOATS = TI_OFF + 620;   // 51672 floats = 206688 B

typedef unsigned long long ull;

__device__ __forceinline__ ull ffma2(ull a, ull b, ull c) {
    ull d;
    asm("fma.rn.f32x2 %0, %1, %2, %3;" : "=l"(d) : "l"(a), "l"(b), "l"(c));
    return d;
}
__device__ __forceinline__ ull pack2(float x) {
    ull r; asm("mov.b64 %0, {%1, %1};" : "=l"(r) : "f"(x)); return r;
}
__device__ __forceinline__ float2 unpack2(ull v) {
    float2 r; asm("mov.b64 {%0, %1}, %2;" : "=f"(r.x), "=f"(r.y) : "l"(v)); return r;
}

__global__ __launch_bounds__(NT, 1) void residual_graph_kernel(
    const float* __restrict__ x,
    const float* __restrict__ gate_w,  const float* __restrict__ gate_b,
    const float* __restrict__ bnlin_w, const float* __restrict__ bnlin_b,
    const float* __restrict__ rel_w1,  const float* __restrict__ rel_b1,
    const float* __restrict__ root_w1,
    const float* __restrict__ rel_w_mid, const float* __restrict__ rel_b_mid,
    const float* __restrict__ root_w_mid,
    float* __restrict__ out)
{
    extern __shared__ float sm[];
    const int b    = blockIdx.x;
    const int tid  = threadIdx.x;
    const int lane = tid & 31;
    const int wid  = tid >> 5;

    // ---------------- Phase 0: load x tile into padded SMEM ----------------
    {
        const float4* xg  = reinterpret_cast<const float4*>(x + (size_t)b * (CN * FIN));
        float4*       xs4 = reinterpret_cast<float4*>(sm + XS_OFF);
        for (int i = tid; i < CN * 64; i += NT) {
            int r = i >> 6, q = i & 63;
            xs4[r * (XS_LD / 4) + q] = xg[i];
        }
        float4 z = make_float4(0.f, 0.f, 0.f, 0.f);
        if (tid < 2 * 64) {
            int r = 62 + (tid >> 6), q = tid & 63;
            xs4[r * (XS_LD / 4) + q] = z;
        }
    }
    __syncthreads();

    // ---- Phase 1: fused quad GEMM  [62,256] x [256,64] x 4 matrices -------
    // grp 0: gate_w -> x_mask, grp 1: bnlin_w -> xa, grp 2: rel_w1 -> A,
    // grp 3: root_w1 -> B.  Columns [cg*4..+3] and [32+cg*4..+3] per thread
    // (contiguous 128B per 8-lane phase -> conflict-free).
    {
        const int grp = tid >> 7;
        const int t7  = tid & 127;
        const int rg  = t7 >> 3;         // rows rg + 16*i
        const int cg  = t7 & 7;
        const int c0a = cg * 4;
        const int c0b = 32 + cg * 4;

        ull a0[4][2], a1[4][2];          // [row][pair] for col groups a and b
        #pragma unroll
        for (int i = 0; i < 4; ++i) {
            a0[i][0] = a0[i][1] = 0ull;
            a1[i][0] = a1[i][1] = 0ull;
        }

        for (int ch = 0; ch < 4; ++ch) {
            {
                const float4* g0 = reinterpret_cast<const float4*>(gate_w)  + ch * 1024;
                const float4* g1 = reinterpret_cast<const float4*>(bnlin_w) + ch * 1024;
                const float4* g2 = reinterpret_cast<const float4*>(rel_w1)  + ch * 1024;
                const float4* g3 = reinterpret_cast<const float4*>(root_w1) + ch * 1024;
                float4* wb4 = reinterpret_cast<float4*>(sm + WB_OFF);
                for (int i = tid; i < 1024; i += NT) {
                    wb4[i]        = g0[i];
                    wb4[1024 + i] = g1[i];
                    wb4[2048 + i] = g2[i];
                    wb4[3072 + i] = g3[i];
                }
            }
            __syncthreads();

            const float* wm  = sm + WB_OFF + grp * 4096;
            const float* xsb = sm + XS_OFF + ch * 64;
            #pragma unroll 2
            for (int kk = 0; kk < 64; kk += 4) {
                float4 xq[4];
                #pragma unroll
                for (int i = 0; i < 4; ++i)
                    xq[i] = *reinterpret_cast<const float4*>(xsb + (rg + 16 * i) * XS_LD + kk);
                #pragma unroll
                for (int k = 0; k < 4; ++k) {
                    ulonglong2 wa = *reinterpret_cast<const ulonglong2*>(wm + (kk + k) * 64 + c0a);
                    ulonglong2 wb = *reinterpret_cast<const ulonglong2*>(wm + (kk + k) * 64 + c0b);
                    #pragma unroll
                    for (int i = 0; i < 4; ++i) {
                        float xs_ = (k == 0) ? xq[i].x : (k == 1) ? xq[i].y
                                  : (k == 2) ? xq[i].z : xq[i].w;
                        ull xd = pack2(xs_);
                        a0[i][0] = ffma2(xd, wa.x, a0[i][0]);
                        a0[i][1] = ffma2(xd, wa.y, a0[i][1]);
                        a1[i][0] = ffma2(xd, wb.x, a1[i][0]);
                        a1[i][1] = ffma2(xd, wb.y, a1[i][1]);
                    }
                }
            }
            __syncthreads();
        }

        // epilogue
        if (grp < 2) {
            const float* bv = grp ? bnlin_b : gate_b;
            float ba[4], bb[4];
            #pragma unroll
            for (int q = 0; q < 4; ++q) { ba[q] = __ldg(&bv[c0a + q]); bb[q] = __ldg(&bv[c0b + q]); }
            float* base = sm + (grp ? HH_OFF : MASK_OFF);
            #pragma unroll
            for (int i = 0; i < 4; ++i) {
                int r = rg + 16 * i;
                float2 v0 = unpack2(a0[i][0]), v1 = unpack2(a0[i][1]);
                float2 v2 = unpack2(a1[i][0]), v3 = unpack2(a1[i][1]);
                float4 ta, tb;
                ta.x = tanhf(v0.x + ba[0]); ta.y = tanhf(v0.y + ba[1]);
                ta.z = tanhf(v1.x + ba[2]); ta.w = tanhf(v1.y + ba[3]);
                tb.x = tanhf(v2.x + bb[0]); tb.y = tanhf(v2.y + bb[1]);
                tb.z = tanhf(v3.x + bb[2]); tb.w = tanhf(v3.y + bb[3]);
                *reinterpret_cast<float4*>(base + r * HB_LD + c0a) = ta;
                *reinterpret_cast<float4*>(base + r * HB_LD + c0b) = tb;
            }
        } else {
            float* base = sm + (grp == 2 ? A_OFF : B_OFF);
            #pragma unroll
            for (int i = 0; i < 4; ++i) {
                int r = rg + 16 * i;
                ulonglong2 pa; pa.x = a0[i][0]; pa.y = a0[i][1];
                ulonglong2 pb; pb.x = a1[i][0]; pb.y = a1[i][1];
                *reinterpret_cast<ulonglong2*>(base + r * HB_LD + c0a) = pa;
                *reinterpret_cast<ulonglong2*>(base + r * HB_LD + c0b) = pb;
            }
        }
    }
    __syncthreads();

    // -------- Phase 2: adjacency logits adj[r][j] = <xa[r], xa[j]> ---------
    // Cols j = jg + 8q: 8-lane phase reads 8 consecutive rows -> conflict-free.
    {
        const int rr = tid >> 3;
        const int jg = tid & 7;
        ull s2[8];
        #pragma unroll
        for (int q = 0; q < 8; ++q) s2[q] = 0ull;
        const float* xa = sm + HH_OFF;
        for (int k = 0; k < HID; k += 4) {
            ulonglong2 a = *reinterpret_cast<const ulonglong2*>(xa + rr * HB_LD + k);
            #pragma unroll
            for (int q = 0; q < 8; ++q) {
                ulonglong2 aj = *reinterpret_cast<const ulonglong2*>(xa + (jg + 8 * q) * HB_LD + k);
                s2[q] = ffma2(a.x, aj.x, s2[q]);
                s2[q] = ffma2(a.y, aj.y, s2[q]);
            }
        }
        float* adj = sm + ADJ_OFF;
        if (rr < CN) {
            #pragma unroll
            for (int q = 0; q < 8; ++q) {
                int j = jg + 8 * q;
                if (j < CN) {
                    float2 v = unpack2(s2[q]);
                    adj[rr * 64 + j] = v.x + v.y;
                }
            }
        }
    }
    __syncthreads();

    // ---------- Phase 3: softmax per row + top-10 selection ----------------
    {
        int* tix = reinterpret_cast<int*>(sm);
        for (int r = wid; r < CN; r += 16) {
            const float* arow = sm + ADJ_OFF + r * 64;
            float a0 = arow[lane];
            bool ok1 = (lane + 32) < CN;
            float a1 = ok1 ? arow[lane + 32] : -1e30f;
            float mx = fmaxf(a0, a1);
            #pragma unroll
            for (int o = 16; o; o >>= 1) mx = fmaxf(mx, __shfl_xor_sync(0xffffffffu, mx, o));
            float e0 = expf(a0 - mx);
            float e1 = ok1 ? expf(a1 - mx) : 0.f;
            float s = e0 + e1;
            #pragma unroll
            for (int o = 16; o; o >>= 1) s += __shfl_xor_sync(0xffffffffu, s, o);
            float inv = 1.f / s;
            float p0 = e0 * inv;
            float p1 = e1 * inv;
            float v0 = p0;
            float v1 = ok1 ? p1 : -1.f;
            for (int m = 0; m < TOPK; ++m) {
                float c  = fmaxf(v0, v1);
                float cm = c;
                #pragma unroll
                for (int o = 16; o; o >>= 1) cm = fmaxf(cm, __shfl_xor_sync(0xffffffffu, cm, o));
                unsigned ball = __ballot_sync(0xffffffffu, c == cm);
                int owner = __ffs(ball) - 1;
                if (lane == owner) {
                    if (v0 == cm) {
                        sm[TV_OFF + r * TOPK + m] = p0;
                        tix[TI_OFF + r * TOPK + m] = lane;
                        v0 = -1.f;
                    } else {
                        sm[TV_OFF + r * TOPK + m] = p1;
                        tix[TI_OFF + r * TOPK + m] = lane + 32;
                        v1 = -1.f;
                    }
                }
            }
        }
    }
    __syncthreads();

    // ---------- Phase 4: h1 = relu(adjS @ A + rel_b1 + B) ------------------
    {
        const int r   = tid >> 3;
        const int cg  = tid & 7;
        const int c0a = cg * 4;
        const int c0b = 32 + cg * 4;
        float* hr0 = sm + HH_OFF + r * HB_LD + c0a;
        float* hr1 = sm + HH_OFF + r * HB_LD + c0b;
        if (r < CN) {
            const int* tix = reinterpret_cast<const int*>(sm);
            ull s[4] = {0ull, 0ull, 0ull, 0ull};
            #pragma unroll
            for (int m = 0; m < TOPK; ++m) {
                int   j = tix[TI_OFF + r * TOPK + m];
                ull  vp = pack2(sm[TV_OFF + r * TOPK + m]);
                ulonglong2 pa = *reinterpret_cast<const ulonglong2*>(sm + A_OFF + j * HB_LD + c0a);
                ulonglong2 pb = *reinterpret_cast<const ulonglong2*>(sm + A_OFF + j * HB_LD + c0b);
                s[0] = ffma2(vp, pa.x, s[0]);
                s[1] = ffma2(vp, pa.y, s[1]);
                s[2] = ffma2(vp, pb.x, s[2]);
                s[3] = ffma2(vp, pb.y, s[3]);
            }
            float4 r0 = *reinterpret_cast<const float4*>(sm + B_OFF + r * HB_LD + c0a);
            float4 r1 = *reinterpret_cast<const float4*>(sm + B_OFF + r * HB_LD + c0b);
            float2 v0 = unpack2(s[0]), v1 = unpack2(s[1]);
            float2 v2 = unpack2(s[2]), v3 = unpack2(s[3]);
            float4 t0, t1;
            t0.x = fmaxf(v0.x + __ldg(&rel_b1[c0a + 0]) + r0.x, 0.f);
            t0.y = fmaxf(v0.y + __ldg(&rel_b1[c0a + 1]) + r0.y, 0.f);
            t0.z = fmaxf(v1.x + __ldg(&rel_b1[c0a + 2]) + r0.z, 0.f);
            t0.w = fmaxf(v1.y + __ldg(&rel_b1[c0a + 3]) + r0.w, 0.f);
            t1.x = fmaxf(v2.x + __ldg(&rel_b1[c0b + 0]) + r1.x, 0.f);
            t1.y = fmaxf(v2.y + __ldg(&rel_b1[c0b + 1]) + r1.y, 0.f);
            t1.z = fmaxf(v3.x + __ldg(&rel_b1[c0b + 2]) + r1.z, 0.f);
            t1.w = fmaxf(v3.y + __ldg(&rel_b1[c0b + 3]) + r1.w, 0.f);
            *reinterpret_cast<float4*>(hr0) = t0;
            *reinterpret_cast<float4*>(hr1) = t1;
        } else {
            float4 z = make_float4(0.f, 0.f, 0.f, 0.f);
            *reinterpret_cast<float4*>(hr0) = z;
            *reinterpret_cast<float4*>(hr1) = z;
        }
    }
    __syncthreads();

    // ---------------- Phase 5: six graph-conv layers -----------------------
    for (int L = 0; L < 6; ++L) {
        {
            const float4* g0 = reinterpret_cast<const float4*>(rel_w_mid)  + L * 1024;
            const float4* g1 = reinterpret_cast<const float4*>(root_w_mid) + L * 1024;
            float4* wb4 = reinterpret_cast<float4*>(sm + WB_OFF);
            for (int i = tid; i < 1024; i += NT) {
                wb4[i]        = g0[i];
                wb4[1024 + i] = g1[i];
            }
        }
        __syncthreads();

        // hr = h @ rel_w (mtx 0 -> A), hroot = h @ root_w (mtx 1 -> B)
        {
            const int mtx = tid >> 8;
            const int t8  = tid & 255;
            const int rg  = t8 >> 3;        // rows rg, rg+32
            const int cg  = t8 & 7;
            const int c0a = cg * 4;
            const int c0b = 32 + cg * 4;

            ull a0[2][2], a1[2][2];
            #pragma unroll
            for (int i = 0; i < 2; ++i) {
                a0[i][0] = a0[i][1] = 0ull;
                a1[i][0] = a1[i][1] = 0ull;
            }

            const float* wm = sm + WB_OFF + mtx * 4096;
            const float* hb = sm + HH_OFF;
            #pragma unroll 2
            for (int kk = 0; kk < HID; kk += 4) {
                float4 hq[2];
                hq[0] = *reinterpret_cast<const float4*>(hb + rg * HB_LD + kk);
                hq[1] = *reinterpret_cast<const float4*>(hb + (rg + 32) * HB_LD + kk);
                #pragma unroll
                for (int k = 0; k < 4; ++k) {
                    ulonglong2 wa = *reinterpret_cast<const ulonglong2*>(wm + (kk + k) * 64 + c0a);
                    ulonglong2 wb = *reinterpret_cast<const ulonglong2*>(wm + (kk + k) * 64 + c0b);
                    #pragma unroll
                    for (int i = 0; i < 2; ++i) {
                        float hs = (k == 0) ? hq[i].x : (k == 1) ? hq[i].y
                                 : (k == 2) ? hq[i].z : hq[i].w;
                        ull hd = pack2(hs);
                        a0[i][0] = ffma2(hd, wa.x, a0[i][0]);
                        a0[i][1] = ffma2(hd, wa.y, a0[i][1]);
                        a1[i][0] = ffma2(hd, wb.x, a1[i][0]);
                        a1[i][1] = ffma2(hd, wb.y, a1[i][1]);
                    }
                }
            }
            float* base = sm + (mtx ? B_OFF : A_OFF);
            #pragma unroll
            for (int i = 0; i < 2; ++i) {
                int r = rg + 32 * i;
                ulonglong2 pa; pa.x = a0[i][0]; pa.y = a0[i][1];
                ulonglong2 pb; pb.x = a1[i][0]; pb.y = a1[i][1];
                *reinterpret_cast<ulonglong2*>(base + r * HB_LD + c0a) = pa;
                *reinterpret_cast<ulonglong2*>(base + r * HB_LD + c0b) = pb;
            }
        }
        __syncthreads();

        // h update: t = relu(adjS @ hr + rel_b_mid[L] + hroot)
        // L<5: h += t; L==5: out = t * mask
        {
            const int r   = tid >> 3;
            const int cg  = tid & 7;
            const int c0a = cg * 4;
            const int c0b = 32 + cg * 4;
            if (r < CN) {
                const int* tix = reinterpret_cast<const int*>(sm);
                const float* relb = rel_b_mid + L * 64;
                ull s[4] = {0ull, 0ull, 0ull, 0ull};
                #pragma unroll
                for (int m = 0; m < TOPK; ++m) {
                    int   j = tix[TI_OFF + r * TOPK + m];
                    ull  vp = pack2(sm[TV_OFF + r * TOPK + m]);
                    ulonglong2 pa = *reinterpret_cast<const ulonglong2*>(sm + A_OFF + j * HB_LD + c0a);
                    ulonglong2 pb = *reinterpret_cast<const ulonglong2*>(sm + A_OFF + j * HB_LD + c0b);
                    s[0] = ffma2(vp, pa.x, s[0]);
                    s[1] = ffma2(vp, pa.y, s[1]);
                    s[2] = ffma2(vp, pb.x, s[2]);
                    s[3] = ffma2(vp, pb.y, s[3]);
                }
                float4 r0 = *reinterpret_cast<const float4*>(sm + B_OFF + r * HB_LD + c0a);
                float4 r1 = *reinterpret_cast<const float4*>(sm + B_OFF + r * HB_LD + c0b);
                float2 v0 = unpack2(s[0]), v1 = unpack2(s[1]);
                float2 v2 = unpack2(s[2]), v3 = unpack2(s[3]);
                float4 t0, t1;
                t0.x = fmaxf(v0.x + __ldg(&relb[c0a + 0]) + r0.x, 0.f);
                t0.y = fmaxf(v0.y + __ldg(&relb[c0a + 1]) + r0.y, 0.f);
                t0.z = fmaxf(v1.x + __ldg(&relb[c0a + 2]) + r0.z, 0.f);
                t0.w = fmaxf(v1.y + __ldg(&relb[c0a + 3]) + r0.w, 0.f);
                t1.x = fmaxf(v2.x + __ldg(&relb[c0b + 0]) + r1.x, 0.f);
                t1.y = fmaxf(v2.y + __ldg(&relb[c0b + 1]) + r1.y, 0.f);
                t1.z = fmaxf(v3.x + __ldg(&relb[c0b + 2]) + r1.z, 0.f);
                t1.w = fmaxf(v3.y + __ldg(&relb[c0b + 3]) + r1.w, 0.f);
                float* h0 = sm + HH_OFF + r * HB_LD + c0a;
                float* h1 = sm + HH_OFF + r * HB_LD + c0b;
                if (L < 5) {
                    float4 ha = *reinterpret_cast<const float4*>(h0);
                    float4 hbv = *reinterpret_cast<const float4*>(h1);
                    ha.x += t0.x; ha.y += t0.y; ha.z += t0.z; ha.w += t0.w;
                    hbv.x += t1.x; hbv.y += t1.y; hbv.z += t1.z; hbv.w += t1.w;
                    *reinterpret_cast<float4*>(h0) = ha;
                    *reinterpret_cast<float4*>(h1) = hbv;
                } else {
                    float4 m0 = *reinterpret_cast<const float4*>(sm + MASK_OFF + r * HB_LD + c0a);
                    float4 m1 = *reinterpret_cast<const float4*>(sm + MASK_OFF + r * HB_LD + c0b);
                    float4 o0, o1;
                    o0.x = t0.x * m0.x; o0.y = t0.y * m0.y; o0.z = t0.z * m0.z; o0.w = t0.w * m0.w;
                    o1.x = t1.x * m1.x; o1.y = t1.y * m1.y; o1.z = t1.z * m1.z; o1.w = t1.w * m1.w;
                    float* og = out + (size_t)b * (CN * HID) + r * HID;
                    *reinterpret_cast<float4*>(og + c0a) = o0;
                    *reinterpret_cast<float4*>(og + c0b) = o1;
                }
            }
        }
        if (L < 5) __syncthreads();
    }
}

extern "C" void kernel_launch(void* const* d_in, const int* in_sizes, int n_in,
                              void* d_out, int out_size) {
    const float* x          = (const float*)d_in[0];
    const float* gate_w     = (const float*)d_in[1];
    const float* gate_b     = (const float*)d_in[2];
    const float* bnlin_w    = (const float*)d_in[3];
    const float* bnlin_b    = (const float*)d_in[4];
    const float* rel_w1     = (const float*)d_in[5];
    const float* rel_b1     = (const float*)d_in[6];
    const float* root_w1    = (const float*)d_in[7];
    const float* rel_w_mid  = (const float*)d_in[8];
    const float* rel_b_mid  = (const float*)d_in[9];
    const float* root_w_mid = (const float*)d_in[10];
    float* out = (float*)d_out;

    (void)in_sizes; (void)n_in; (void)out_size;

    const int smem_bytes = SMEM_FLOATS * 4;
    cudaFuncSetAttribute(residual_graph_kernel,
                         cudaFuncAttributeMaxDynamicSharedMemorySize, smem_bytes);
    residual_graph_kernel<<<NB, NT, smem_bytes>>>(
        x, gate_w, gate_b, bnlin_w, bnlin_b, rel_w1, rel_b1, root_w1,
        rel_w_mid, rel_b_mid, root_w_mid, out);
}

// round 8
// speedup vs baseline: 2.7383x; 1.4846x over previous
#include <cuda_runtime.h>

// Problem constants
static constexpr int NB   = 4096;
static constexpr int CN   = 62;
static constexpr int FIN  = 256;
static constexpr int HID  = 64;
static constexpr int TOPK = 10;
static constexpr int NT   = 512;

// SMEM strides (floats)
static constexpr int XS_LD = 260;  // x tile stride (bank = (4r+k)%32 distinct for mma A-frags)
static constexpr int HB_LD = 68;   // [64,64] buffers + transposed weights (bank-distinct frags)

// SMEM layout (floats)
static constexpr int XS_OFF   = 0;                  // 64*260 = 16640 (x; ADJ overlays later)
static constexpr int ADJ_OFF  = 0;
static constexpr int WB_OFF   = 16640;              // 5 slots x 4352 = 21760 (W^T tf32)
static constexpr int WSLOT    = 4352;               // 64 n-rows x 68
static constexpr int MASK_OFF = WB_OFF + 21760;     // 38400
static constexpr int HH_OFF   = MASK_OFF + 4352;    // 42752 (xa then h)
static constexpr int A_OFF    = HH_OFF + 4352;      // 47104 (xr / hr)
static constexpr int B_OFF    = A_OFF + 4352;       // 51456 (xroot / hroot)
static constexpr int TV_OFF   = B_OFF + 4352;       // 55808
static constexpr int TI_OFF   = TV_OFF + 620;       // 56428
static constexpr int SMEM_FLOATS = TI_OFF + 620;    // 57048 fl = 228192 B

typedef unsigned long long ull;
typedef unsigned int uint32;

__device__ __forceinline__ ull ffma2(ull a, ull b, ull c) {
    ull d; asm("fma.rn.f32x2 %0, %1, %2, %3;" : "=l"(d) : "l"(a), "l"(b), "l"(c)); return d;
}
__device__ __forceinline__ ull pack2(float x) {
    ull r; asm("mov.b64 %0, {%1, %1};" : "=l"(r) : "f"(x)); return r;
}
__device__ __forceinline__ float2 unpack2(ull v) {
    float2 r; asm("mov.b64 {%0, %1}, %2;" : "=f"(r.x), "=f"(r.y) : "l"(v)); return r;
}
__device__ __forceinline__ uint32 cvt_tf32(float x) {
    uint32 r; asm("cvt.rna.tf32.f32 %0, %1;" : "=r"(r) : "f"(x)); return r;
}
// D += A(16x8) * B(8x8), tf32 inputs, fp32 accum.
__device__ __forceinline__ void mma_tf32(float d[4], uint32 a0, uint32 a1, uint32 a2, uint32 a3,
                                         uint32 b0, uint32 b1) {
    asm volatile(
        "mma.sync.aligned.m16n8k8.row.col.f32.tf32.tf32.f32 "
        "{%0,%1,%2,%3}, {%4,%5,%6,%7}, {%8,%9}, {%0,%1,%2,%3};"
        : "+f"(d[0]), "+f"(d[1]), "+f"(d[2]), "+f"(d[3])
        : "r"(a0), "r"(a1), "r"(a2), "r"(a3), "r"(b0), "r"(b1));
}

__global__ __launch_bounds__(NT, 1) void residual_graph_kernel(
    const float* __restrict__ x,
    const float* __restrict__ gate_w,  const float* __restrict__ gate_b,
    const float* __restrict__ bnlin_w, const float* __restrict__ bnlin_b,
    const float* __restrict__ rel_w1,  const float* __restrict__ rel_b1,
    const float* __restrict__ root_w1,
    const float* __restrict__ rel_w_mid, const float* __restrict__ rel_b_mid,
    const float* __restrict__ root_w_mid,
    float* __restrict__ out)
{
    extern __shared__ float sm[];
    const int b    = blockIdx.x;
    const int tid  = threadIdx.x;
    const int lane = tid & 31;
    const int wid  = tid >> 5;

    // ---------------- Phase 0: load x tile ----------------
    {
        const float4* xg  = reinterpret_cast<const float4*>(x + (size_t)b * (CN * FIN));
        float4*       xs4 = reinterpret_cast<float4*>(sm + XS_OFF);
        for (int i = tid; i < CN * 64; i += NT) {
            int r = i >> 6, q = i & 63;
            xs4[r * (XS_LD / 4) + q] = xg[i];
        }
        float4 z = make_float4(0.f, 0.f, 0.f, 0.f);
        if (tid < 2 * 64) {
            int r = 62 + (tid >> 6), q = tid & 63;
            xs4[r * (XS_LD / 4) + q] = z;
        }
    }
    __syncthreads();

    // ---- Phase 1: four [62,256]x[256,64] GEMMs via mma.sync tf32 ----------
    // Slots in WB (W^T, [n][k] stride 68): 0 gate, 1 rel, 2 root, 3 bnlin_hi, 4 bnlin_lo.
    // Warps 0-7: bnlin split-unit (3 mma/step), ms=wid>>1, nh=wid&1.
    // Warps 8-15: 3 light units each of {gate,rel,root} x ms x nh.
    {
        const int lr = lane >> 2;       // 0..7
        const int lk = lane & 3;        // 0..3
        float dB[4][4];                 // bnlin unit accs (warps 0-7)
        float dL[3][4][4];              // light unit accs (warps 8-15)
        #pragma unroll
        for (int t = 0; t < 4; ++t)
            #pragma unroll
            for (int i = 0; i < 4; ++i) dB[t][i] = 0.f;
        #pragma unroll
        for (int u = 0; u < 3; ++u)
            #pragma unroll
            for (int t = 0; t < 4; ++t)
                #pragma unroll
                for (int i = 0; i < 4; ++i) dL[u][t][i] = 0.f;

        for (int ch = 0; ch < 4; ++ch) {
            // stage transposed tf32 weight chunk (k-slice ch*64..+63)
            for (int idx = tid; idx < 4096; idx += NT) {
                int k = idx >> 6, n = idx & 63;
                int gsrc = (ch * 64 + k) * 64 + n;
                float g = __ldg(&gate_w[gsrc]);
                float r = __ldg(&rel_w1[gsrc]);
                float o = __ldg(&root_w1[gsrc]);
                float bn = __ldg(&bnlin_w[gsrc]);
                uint32 hi = cvt_tf32(bn);
                float lo = bn - __uint_as_float(hi);
                int dsti = n * HB_LD + k;
                sm[WB_OFF + 0 * WSLOT + dsti] = __uint_as_float(cvt_tf32(g));
                sm[WB_OFF + 1 * WSLOT + dsti] = __uint_as_float(cvt_tf32(r));
                sm[WB_OFF + 2 * WSLOT + dsti] = __uint_as_float(cvt_tf32(o));
                sm[WB_OFF + 3 * WSLOT + dsti] = __uint_as_float(hi);
                sm[WB_OFF + 4 * WSLOT + dsti] = __uint_as_float(cvt_tf32(lo));
            }
            __syncthreads();

            if (wid < 8) {
                // bnlin split unit
                const int ms = wid >> 1, nh = wid & 1;
                const int r0 = ms * 16 + lr;
                const float* whi = sm + WB_OFF + 3 * WSLOT;
                const float* wlo = sm + WB_OFF + 4 * WSLOT;
                #pragma unroll
                for (int step = 0; step < 8; ++step) {
                    int kc = ch * 64 + step * 8 + lk;
                    float x0 = sm[XS_OFF + r0 * XS_LD + kc];
                    float x1 = sm[XS_OFF + (r0 + 8) * XS_LD + kc];
                    float x2 = sm[XS_OFF + r0 * XS_LD + kc + 4];
                    float x3 = sm[XS_OFF + (r0 + 8) * XS_LD + kc + 4];
                    uint32 h0 = cvt_tf32(x0), h1 = cvt_tf32(x1), h2 = cvt_tf32(x2), h3 = cvt_tf32(x3);
                    uint32 l0 = cvt_tf32(x0 - __uint_as_float(h0));
                    uint32 l1 = cvt_tf32(x1 - __uint_as_float(h1));
                    uint32 l2 = cvt_tf32(x2 - __uint_as_float(h2));
                    uint32 l3 = cvt_tf32(x3 - __uint_as_float(h3));
                    int kw = step * 8 + lk;
                    #pragma unroll
                    for (int t = 0; t < 4; ++t) {
                        int n = nh * 32 + t * 8 + lr;
                        uint32 bh0 = __float_as_uint(whi[n * HB_LD + kw]);
                        uint32 bh1 = __float_as_uint(whi[n * HB_LD + kw + 4]);
                        uint32 bl0 = __float_as_uint(wlo[n * HB_LD + kw]);
                        uint32 bl1 = __float_as_uint(wlo[n * HB_LD + kw + 4]);
                        mma_tf32(dB[t], h0, h1, h2, h3, bh0, bh1);
                        mma_tf32(dB[t], h0, h1, h2, h3, bl0, bl1);
                        mma_tf32(dB[t], l0, l1, l2, l3, bh0, bh1);
                    }
                }
            } else {
                // 3 light units: u_global = (wid-8)*3 + u : mat = u>>3, ms = (u&7)>>1, nh = u&1
                #pragma unroll
                for (int u = 0; u < 3; ++u) {
                    int ug  = (wid - 8) * 3 + u;
                    int mat = ug >> 3, ms = (ug & 7) >> 1, nh = ug & 1;
                    const int r0 = ms * 16 + lr;
                    const float* wt = sm + WB_OFF + mat * WSLOT;
                    #pragma unroll
                    for (int step = 0; step < 8; ++step) {
                        int kc = ch * 64 + step * 8 + lk;
                        uint32 a0 = cvt_tf32(sm[XS_OFF + r0 * XS_LD + kc]);
                        uint32 a1 = cvt_tf32(sm[XS_OFF + (r0 + 8) * XS_LD + kc]);
                        uint32 a2 = cvt_tf32(sm[XS_OFF + r0 * XS_LD + kc + 4]);
                        uint32 a3 = cvt_tf32(sm[XS_OFF + (r0 + 8) * XS_LD + kc + 4]);
                        int kw = step * 8 + lk;
                        #pragma unroll
                        for (int t = 0; t < 4; ++t) {
                            int n = nh * 32 + t * 8 + lr;
                            uint32 b0 = __float_as_uint(wt[n * HB_LD + kw]);
                            uint32 b1 = __float_as_uint(wt[n * HB_LD + kw + 4]);
                            mma_tf32(dL[u][t], a0, a1, a2, a3, b0, b1);
                        }
                    }
                }
            }
            __syncthreads();
        }

        // epilogue: D frags -> smem buffers
        if (wid < 8) {
            const int ms = wid >> 1, nh = wid & 1;
            int rb = ms * 16 + lr;
            #pragma unroll
            for (int t = 0; t < 4; ++t) {
                int cb = nh * 32 + t * 8 + lk * 2;
                float b0v = __ldg(&bnlin_b[cb]), b1v = __ldg(&bnlin_b[cb + 1]);
                float2 lo_, hi_;
                lo_.x = tanhf(dB[t][0] + b0v); lo_.y = tanhf(dB[t][1] + b1v);
                hi_.x = tanhf(dB[t][2] + b0v); hi_.y = tanhf(dB[t][3] + b1v);
                *reinterpret_cast<float2*>(sm + HH_OFF + rb * HB_LD + cb)       = lo_;
                *reinterpret_cast<float2*>(sm + HH_OFF + (rb + 8) * HB_LD + cb) = hi_;
            }
        } else {
            #pragma unroll
            for (int u = 0; u < 3; ++u) {
                int ug  = (wid - 8) * 3 + u;
                int mat = ug >> 3, ms = (ug & 7) >> 1, nh = ug & 1;
                int rb = ms * 16 + lr;
                #pragma unroll
                for (int t = 0; t < 4; ++t) {
                    int cb = nh * 32 + t * 8 + lk * 2;
                    if (mat == 0) {
                        float b0v = __ldg(&gate_b[cb]), b1v = __ldg(&gate_b[cb + 1]);
                        float2 lo_, hi_;
                        lo_.x = tanhf(dL[u][t][0] + b0v); lo_.y = tanhf(dL[u][t][1] + b1v);
                        hi_.x = tanhf(dL[u][t][2] + b0v); hi_.y = tanhf(dL[u][t][3] + b1v);
                        *reinterpret_cast<float2*>(sm + MASK_OFF + rb * HB_LD + cb)       = lo_;
                        *reinterpret_cast<float2*>(sm + MASK_OFF + (rb + 8) * HB_LD + cb) = hi_;
                    } else {
                        float* base = sm + (mat == 1 ? A_OFF : B_OFF);
                        float2 lo_, hi_;
                        lo_.x = dL[u][t][0]; lo_.y = dL[u][t][1];
                        hi_.x = dL[u][t][2]; hi_.y = dL[u][t][3];
                        *reinterpret_cast<float2*>(base + rb * HB_LD + cb)       = lo_;
                        *reinterpret_cast<float2*>(base + (rb + 8) * HB_LD + cb) = hi_;
                    }
                }
            }
        }
    }
    __syncthreads();

    // -------- Phase 2: adjacency logits (fp32 exact, f32x2) ---------------
    {
        const int rr = tid >> 3;
        const int jg = tid & 7;
        ull s2[8];
        #pragma unroll
        for (int q = 0; q < 8; ++q) s2[q] = 0ull;
        const float* xa = sm + HH_OFF;
        for (int k = 0; k < HID; k += 4) {
            ulonglong2 a = *reinterpret_cast<const ulonglong2*>(xa + rr * HB_LD + k);
            #pragma unroll
            for (int q = 0; q < 8; ++q) {
                ulonglong2 aj = *reinterpret_cast<const ulonglong2*>(xa + (jg + 8 * q) * HB_LD + k);
                s2[q] = ffma2(a.x, aj.x, s2[q]);
                s2[q] = ffma2(a.y, aj.y, s2[q]);
            }
        }
        float* adj = sm + ADJ_OFF;
        if (rr < CN) {
            #pragma unroll
            for (int q = 0; q < 8; ++q) {
                int j = jg + 8 * q;
                if (j < CN) {
                    float2 v = unpack2(s2[q]);
                    adj[rr * 64 + j] = v.x + v.y;
                }
            }
        }
    }
    __syncthreads();

    // ---------- Phase 3: softmax + top-10 ----------------------------------
    {
        int* tix = reinterpret_cast<int*>(sm);
        for (int r = wid; r < CN; r += 16) {
            const float* arow = sm + ADJ_OFF + r * 64;
            float a0 = arow[lane];
            bool ok1 = (lane + 32) < CN;
            float a1 = ok1 ? arow[lane + 32] : -1e30f;
            float mx = fmaxf(a0, a1);
            #pragma unroll
            for (int o = 16; o; o >>= 1) mx = fmaxf(mx, __shfl_xor_sync(0xffffffffu, mx, o));
            float e0 = expf(a0 - mx);
            float e1 = ok1 ? expf(a1 - mx) : 0.f;
            float s = e0 + e1;
            #pragma unroll
            for (int o = 16; o; o >>= 1) s += __shfl_xor_sync(0xffffffffu, s, o);
            float inv = 1.f / s;
            float p0 = e0 * inv, p1 = e1 * inv;
            float v0 = p0;
            float v1 = ok1 ? p1 : -1.f;
            for (int m = 0; m < TOPK; ++m) {
                float c  = fmaxf(v0, v1);
                float cm = c;
                #pragma unroll
                for (int o = 16; o; o >>= 1) cm = fmaxf(cm, __shfl_xor_sync(0xffffffffu, cm, o));
                unsigned ball = __ballot_sync(0xffffffffu, c == cm);
                int owner = __ffs(ball) - 1;
                if (lane == owner) {
                    if (v0 == cm) {
                        sm[TV_OFF + r * TOPK + m] = p0;
                        tix[TI_OFF + r * TOPK + m] = lane;
                        v0 = -1.f;
                    } else {
                        sm[TV_OFF + r * TOPK + m] = p1;
                        tix[TI_OFF + r * TOPK + m] = lane + 32;
                        v1 = -1.f;
                    }
                }
            }
        }
    }
    __syncthreads();

    // ---------- Phase 4: h1 = relu(adjS @ A + rel_b1 + B) ------------------
    {
        const int r   = tid >> 3;
        const int cg  = tid & 7;
        const int c0a = cg * 4;
        const int c0b = 32 + cg * 4;
        float* hr0 = sm + HH_OFF + r * HB_LD + c0a;
        float* hr1 = sm + HH_OFF + r * HB_LD + c0b;
        if (r < CN) {
            const int* tix = reinterpret_cast<const int*>(sm);
            ull s[4] = {0ull, 0ull, 0ull, 0ull};
            #pragma unroll
            for (int m = 0; m < TOPK; ++m) {
                int   j = tix[TI_OFF + r * TOPK + m];
                ull  vp = pack2(sm[TV_OFF + r * TOPK + m]);
                ulonglong2 pa = *reinterpret_cast<const ulonglong2*>(sm + A_OFF + j * HB_LD + c0a);
                ulonglong2 pb = *reinterpret_cast<const ulonglong2*>(sm + A_OFF + j * HB_LD + c0b);
                s[0] = ffma2(vp, pa.x, s[0]);
                s[1] = ffma2(vp, pa.y, s[1]);
                s[2] = ffma2(vp, pb.x, s[2]);
                s[3] = ffma2(vp, pb.y, s[3]);
            }
            float4 r0 = *reinterpret_cast<const float4*>(sm + B_OFF + r * HB_LD + c0a);
            float4 r1 = *reinterpret_cast<const float4*>(sm + B_OFF + r * HB_LD + c0b);
            float2 v0 = unpack2(s[0]), v1 = unpack2(s[1]);
            float2 v2 = unpack2(s[2]), v3 = unpack2(s[3]);
            float4 t0, t1;
            t0.x = fmaxf(v0.x + __ldg(&rel_b1[c0a + 0]) + r0.x, 0.f);
            t0.y = fmaxf(v0.y + __ldg(&rel_b1[c0a + 1]) + r0.y, 0.f);
            t0.z = fmaxf(v1.x + __ldg(&rel_b1[c0a + 2]) + r0.z, 0.f);
            t0.w = fmaxf(v1.y + __ldg(&rel_b1[c0a + 3]) + r0.w, 0.f);
            t1.x = fmaxf(v2.x + __ldg(&rel_b1[c0b + 0]) + r1.x, 0.f);
            t1.y = fmaxf(v2.y + __ldg(&rel_b1[c0b + 1]) + r1.y, 0.f);
            t1.z = fmaxf(v3.x + __ldg(&rel_b1[c0b + 2]) + r1.z, 0.f);
            t1.w = fmaxf(v3.y + __ldg(&rel_b1[c0b + 3]) + r1.w, 0.f);
            *reinterpret_cast<float4*>(hr0) = t0;
            *reinterpret_cast<float4*>(hr1) = t1;
        } else {
            float4 z = make_float4(0.f, 0.f, 0.f, 0.f);
            *reinterpret_cast<float4*>(hr0) = z;
            *reinterpret_cast<float4*>(hr1) = z;
        }
    }
    __syncthreads();

    // ---------------- Phase 5: six layers (mma GEMMs + fp32 gather) --------
    for (int L = 0; L < 6; ++L) {
        // stage transposed tf32 mid weights: slot 0 rel, slot 1 root
        for (int idx = tid; idx < 4096; idx += NT) {
            int k = idx >> 6, n = idx & 63;
            float rw = __ldg(&rel_w_mid[L * 4096 + k * 64 + n]);
            float ow = __ldg(&root_w_mid[L * 4096 + k * 64 + n]);
            int dsti = n * HB_LD + k;
            sm[WB_OFF + 0 * WSLOT + dsti] = __uint_as_float(cvt_tf32(rw));
            sm[WB_OFF + 1 * WSLOT + dsti] = __uint_as_float(cvt_tf32(ow));
        }
        __syncthreads();

        // GEMM: 16 units = mat(2) x ms(4) x nh(2); warp -> one unit
        {
            const int mat = wid >> 3, ms = (wid >> 1) & 3, nh = wid & 1;
            const int lr = lane >> 2, lk = lane & 3;
            const int r0 = ms * 16 + lr;
            const float* wt = sm + WB_OFF + mat * WSLOT;
            const float* hb = sm + HH_OFF;
            float d[4][4];
            #pragma unroll
            for (int t = 0; t < 4; ++t)
                #pragma unroll
                for (int i = 0; i < 4; ++i) d[t][i] = 0.f;
            #pragma unroll
            for (int step = 0; step < 8; ++step) {
                int kc = step * 8 + lk;
                uint32 a0 = cvt_tf32(hb[r0 * HB_LD + kc]);
                uint32 a1 = cvt_tf32(hb[(r0 + 8) * HB_LD + kc]);
                uint32 a2 = cvt_tf32(hb[r0 * HB_LD + kc + 4]);
                uint32 a3 = cvt_tf32(hb[(r0 + 8) * HB_LD + kc + 4]);
                #pragma unroll
                for (int t = 0; t < 4; ++t) {
                    int n = nh * 32 + t * 8 + lr;
                    uint32 b0 = __float_as_uint(wt[n * HB_LD + kc]);
                    uint32 b1 = __float_as_uint(wt[n * HB_LD + kc + 4]);
                    mma_tf32(d[t], a0, a1, a2, a3, b0, b1);
                }
            }
            float* base = sm + (mat ? B_OFF : A_OFF);
            int rb = ms * 16 + lr;
            #pragma unroll
            for (int t = 0; t < 4; ++t) {
                int cb = nh * 32 + t * 8 + lk * 2;
                float2 lo_, hi_;
                lo_.x = d[t][0]; lo_.y = d[t][1];
                hi_.x = d[t][2]; hi_.y = d[t][3];
                *reinterpret_cast<float2*>(base + rb * HB_LD + cb)       = lo_;
                *reinterpret_cast<float2*>(base + (rb + 8) * HB_LD + cb) = hi_;
            }
        }
        __syncthreads();

        // update: t = relu(adjS @ hr + rel_b_mid[L] + hroot); h+=t / out
        {
            const int r   = tid >> 3;
            const int cg  = tid & 7;
            const int c0a = cg * 4;
            const int c0b = 32 + cg * 4;
            if (r < CN) {
                const int* tix = reinterpret_cast<const int*>(sm);
                const float* relb = rel_b_mid + L * 64;
                ull s[4] = {0ull, 0ull, 0ull, 0ull};
                #pragma unroll
                for (int m = 0; m < TOPK; ++m) {
                    int   j = tix[TI_OFF + r * TOPK + m];
                    ull  vp = pack2(sm[TV_OFF + r * TOPK + m]);
                    ulonglong2 pa = *reinterpret_cast<const ulonglong2*>(sm + A_OFF + j * HB_LD + c0a);
                    ulonglong2 pb = *reinterpret_cast<const ulonglong2*>(sm + A_OFF + j * HB_LD + c0b);
                    s[0] = ffma2(vp, pa.x, s[0]);
                    s[1] = ffma2(vp, pa.y, s[1]);
                    s[2] = ffma2(vp, pb.x, s[2]);
                    s[3] = ffma2(vp, pb.y, s[3]);
                }
                float4 r0 = *reinterpret_cast<const float4*>(sm + B_OFF + r * HB_LD + c0a);
                float4 r1 = *reinterpret_cast<const float4*>(sm + B_OFF + r * HB_LD + c0b);
                float2 v0 = unpack2(s[0]), v1 = unpack2(s[1]);
                float2 v2 = unpack2(s[2]), v3 = unpack2(s[3]);
                float4 t0, t1;
                t0.x = fmaxf(v0.x + __ldg(&relb[c0a + 0]) + r0.x, 0.f);
                t0.y = fmaxf(v0.y + __ldg(&relb[c0a + 1]) + r0.y, 0.f);
                t0.z = fmaxf(v1.x + __ldg(&relb[c0a + 2]) + r0.z, 0.f);
                t0.w = fmaxf(v1.y + __ldg(&relb[c0a + 3]) + r0.w, 0.f);
                t1.x = fmaxf(v2.x + __ldg(&relb[c0b + 0]) + r1.x, 0.f);
                t1.y = fmaxf(v2.y + __ldg(&relb[c0b + 1]) + r1.y, 0.f);
                t1.z = fmaxf(v3.x + __ldg(&relb[c0b + 2]) + r1.z, 0.f);
                t1.w = fmaxf(v3.y + __ldg(&relb[c0b + 3]) + r1.w, 0.f);
                float* h0 = sm + HH_OFF + r * HB_LD + c0a;
                float* h1 = sm + HH_OFF + r * HB_LD + c0b;
                if (L < 5) {
                    float4 ha = *reinterpret_cast<const float4*>(h0);
                    float4 hbv = *reinterpret_cast<const float4*>(h1);
                    ha.x += t0.x; ha.y += t0.y; ha.z += t0.z; ha.w += t0.w;
                    hbv.x += t1.x; hbv.y += t1.y; hbv.z += t1.z; hbv.w += t1.w;
                    *reinterpret_cast<float4*>(h0) = ha;
                    *reinterpret_cast<float4*>(h1) = hbv;
                } else {
                    float4 m0 = *reinterpret_cast<const float4*>(sm + MASK_OFF + r * HB_LD + c0a);
                    float4 m1 = *reinterpret_cast<const float4*>(sm + MASK_OFF + r * HB_LD + c0b);
                    float4 o0, o1;
                    o0.x = t0.x * m0.x; o0.y = t0.y * m0.y; o0.z = t0.z * m0.z; o0.w = t0.w * m0.w;
                    o1.x = t1.x * m1.x; o1.y = t1.y * m1.y; o1.z = t1.z * m1.z; o1.w = t1.w * m1.w;
                    float* og = out + (size_t)b * (CN * HID) + r * HID;
                    *reinterpret_cast<float4*>(og + c0a) = o0;
                    *reinterpret_cast<float4*>(og + c0b) = o1;
                }
            }
        }
        if (L < 5) __syncthreads();
    }
}

extern "C" void kernel_launch(void* const* d_in, const int* in_sizes, int n_in,
                              void* d_out, int out_size) {
    const float* x          = (const float*)d_in[0];
    const float* gate_w     = (const float*)d_in[1];
    const float* gate_b     = (const float*)d_in[2];
    const float* bnlin_w    = (const float*)d_in[3];
    const float* bnlin_b    = (const float*)d_in[4];
    const float* rel_w1     = (const float*)d_in[5];
    const float* rel_b1     = (const float*)d_in[6];
    const float* root_w1    = (const float*)d_in[7];
    const float* rel_w_mid  = (const float*)d_in[8];
    const float* rel_b_mid  = (const float*)d_in[9];
    const float* root_w_mid = (const float*)d_in[10];
    float* out = (float*)d_out;

    (void)in_sizes; (void)n_in; (void)out_size;

    const int smem_bytes = SMEM_FLOATS * 4;   // 228192
    cudaFuncSetAttribute(residual_graph_kernel,
                         cudaFuncAttributeMaxDynamicSharedMemorySize, smem_bytes);
    residual_graph_kernel<<<NB, NT, smem_bytes>>>(
        x, gate_w, gate_b, bnlin_w, bnlin_b, rel_w1, rel_b1, root_w1,
        rel_w_mid, rel_b_mid, root_w_mid, out);
}

// round 10
// speedup vs baseline: 3.2102x; 1.1723x over previous
#include <cuda_runtime.h>

// Problem constants
static constexpr int NB   = 4096;
static constexpr int CN   = 62;
static constexpr int FIN  = 256;
static constexpr int HID  = 64;
static constexpr int TOPK = 10;
static constexpr int NT   = 512;

// SMEM strides (floats)
static constexpr int XS_LD = 260;
static constexpr int HB_LD = 68;

// SMEM layout (floats)
static constexpr int XS_OFF   = 0;                  // 16640 (x; ADJ overlays later)
static constexpr int ADJ_OFF  = 0;
static constexpr int WB_OFF   = 16640;              // 5 x 4352 = 21760 (W^T tf32 staging)
static constexpr int WSLOT    = 4352;
static constexpr int MASK_OFF = WB_OFF + 21760;     // 38400
static constexpr int HH_OFF   = MASK_OFF + 4352;    // 42752 (xa then h)
static constexpr int A_OFF    = HH_OFF + 4352;      // 47104
static constexpr int B_OFF    = A_OFF + 4352;       // 51456
static constexpr int TV_OFF   = B_OFF + 4352;       // 55808
static constexpr int TI_OFF   = TV_OFF + 620;       // 56428
static constexpr int SMEM_FLOATS = TI_OFF + 620;    // 57048 fl = 228192 B

// Pre-transposed tf32 weights in device global:
//   [0..5) x 16384 : gate_T, rel_T, root_T, bnlin_hi_T, bnlin_lo_T   ([n=64][k=256])
//   81920  + L*4096 : rel_mid_T[L]   ([n=64][k=64])
//   106496 + L*4096 : root_mid_T[L]
static constexpr int W1SLOT_F  = 16384;
static constexpr int MIDREL_F  = 5 * W1SLOT_F;          // 81920
static constexpr int MIDROOT_F = MIDREL_F + 6 * 4096;   // 106496
static constexpr int WT_FLOATS = MIDROOT_F + 6 * 4096;  // 131072
__device__ float g_wT[WT_FLOATS];

typedef unsigned long long ull;
typedef unsigned int uint32;

__device__ __forceinline__ ull ffma2(ull a, ull b, ull c) {
    ull d; asm("fma.rn.f32x2 %0, %1, %2, %3;" : "=l"(d) : "l"(a), "l"(b), "l"(c)); return d;
}
__device__ __forceinline__ ull pack2(float x) {
    ull r; asm("mov.b64 %0, {%1, %1};" : "=l"(r) : "f"(x)); return r;
}
__device__ __forceinline__ float2 unpack2(ull v) {
    float2 r; asm("mov.b64 {%0, %1}, %2;" : "=f"(r.x), "=f"(r.y) : "l"(v)); return r;
}
__device__ __forceinline__ uint32 cvt_tf32(float x) {
    uint32 r; asm("cvt.rna.tf32.f32 %0, %1;" : "=r"(r) : "f"(x)); return r;
}
__device__ __forceinline__ void mma_tf32(float d[4], uint32 a0, uint32 a1, uint32 a2, uint32 a3,
                                         uint32 b0, uint32 b1) {
    asm volatile(
        "mma.sync.aligned.m16n8k8.row.col.f32.tf32.tf32.f32 "
        "{%0,%1,%2,%3}, {%4,%5,%6,%7}, {%8,%9}, {%0,%1,%2,%3};"
        : "+f"(d[0]), "+f"(d[1]), "+f"(d[2]), "+f"(d[3])
        : "r"(a0), "r"(a1), "r"(a2), "r"(a3), "r"(b0), "r"(b1));
}

// ---- prep kernel: transpose + tf32-convert all weights once per launch ----
__global__ void prep_weights(
    const float* __restrict__ gate_w,  const float* __restrict__ bnlin_w,
    const float* __restrict__ rel_w1,  const float* __restrict__ root_w1,
    const float* __restrict__ rel_w_mid, const float* __restrict__ root_w_mid)
{
    int i = blockIdx.x * blockDim.x + threadIdx.x;
    if (i < 16384) {
        int n = i >> 8, k = i & 255;
        int src = k * 64 + n;
        int dst = n * 256 + k;
        g_wT[0 * W1SLOT_F + dst] = __uint_as_float(cvt_tf32(__ldg(&gate_w[src])));
        g_wT[1 * W1SLOT_F + dst] = __uint_as_float(cvt_tf32(__ldg(&rel_w1[src])));
        g_wT[2 * W1SLOT_F + dst] = __uint_as_float(cvt_tf32(__ldg(&root_w1[src])));
        float bn = __ldg(&bnlin_w[src]);
        uint32 hi = cvt_tf32(bn);
        g_wT[3 * W1SLOT_F + dst] = __uint_as_float(hi);
        g_wT[4 * W1SLOT_F + dst] = __uint_as_float(cvt_tf32(bn - __uint_as_float(hi)));
    }
    if (i < 24576) {
        int L = i >> 12, idx = i & 4095;
        int n = idx >> 6, k = idx & 63;
        int src = L * 4096 + k * 64 + n;
        int dst = L * 4096 + n * 64 + k;
        g_wT[MIDREL_F + dst]  = __uint_as_float(cvt_tf32(__ldg(&rel_w_mid[src])));
        g_wT[MIDROOT_F + dst] = __uint_as_float(cvt_tf32(__ldg(&root_w_mid[src])));
    }
}

__global__ __launch_bounds__(NT, 1) void residual_graph_kernel(
    const float* __restrict__ x,
    const float* __restrict__ gate_b,
    const float* __restrict__ bnlin_b,
    const float* __restrict__ rel_b1,
    const float* __restrict__ rel_b_mid,
    float* __restrict__ out)
{
    extern __shared__ float sm[];
    const int b    = blockIdx.x;
    const int tid  = threadIdx.x;
    const int lane = tid & 31;
    const int wid  = tid >> 5;

    const float4* wT4 = reinterpret_cast<const float4*>(g_wT);
    float4* wb4 = reinterpret_cast<float4*>(sm + WB_OFF);   // WB_OFF%4==0

    // ---------------- Phase 0: load x tile ----------------
    {
        const float4* xg  = reinterpret_cast<const float4*>(x + (size_t)b * (CN * FIN));
        float4*       xs4 = reinterpret_cast<float4*>(sm + XS_OFF);
        for (int i = tid; i < CN * 64; i += NT) {
            int r = i >> 6, q = i & 63;
            xs4[r * (XS_LD / 4) + q] = xg[i];
        }
        float4 z = make_float4(0.f, 0.f, 0.f, 0.f);
        if (tid < 2 * 64) {
            int r = 62 + (tid >> 6), q = tid & 63;
            xs4[r * (XS_LD / 4) + q] = z;
        }
    }
    __syncthreads();

    // ---- Phase 1: four [62,256]x[256,64] GEMMs via mma.sync tf32 ----------
    // WB slots: 0 gate, 1 rel, 2 root, 3 bnlin_hi, 4 bnlin_lo.
    // Warps 0-7: bnlin split unit (ms=wid>>1, nh=wid&1), 3 mma per (step,t).
    // Warps 8-15: (ms = lw&3, nh = lw>>2), all 3 light matrices share A-frags.
    {
        const int lr = lane >> 2;       // 0..7
        const int lk = lane & 3;        // 0..3
        float dB[4][4];                 // bnlin accs (warps 0-7)
        float dL[3][4][4];              // light accs  (warps 8-15)
        #pragma unroll
        for (int t = 0; t < 4; ++t)
            #pragma unroll
            for (int i = 0; i < 4; ++i) dB[t][i] = 0.f;
        #pragma unroll
        for (int u = 0; u < 3; ++u)
            #pragma unroll
            for (int t = 0; t < 4; ++t)
                #pragma unroll
                for (int i = 0; i < 4; ++i) dL[u][t][i] = 0.f;

        for (int ch = 0; ch < 4; ++ch) {
            // stage 5 pre-transposed tf32 weight chunks, float4, conflict-free
            for (int g = tid; g < 1024; g += NT) {
                int n = g >> 4, kq = g & 15;
                int srcb = n * 64 + ch * 16 + kq;    // f4 index in [n=64][k=256] slot
                int dst  = n * 17 + kq;              // f4 index at stride HB_LD/4=17
                wb4[0 * 1088 + dst] = wT4[0 * 4096 + srcb];
                wb4[1 * 1088 + dst] = wT4[1 * 4096 + srcb];
                wb4[2 * 1088 + dst] = wT4[2 * 4096 + srcb];
                wb4[3 * 1088 + dst] = wT4[3 * 4096 + srcb];
                wb4[4 * 1088 + dst] = wT4[4 * 4096 + srcb];
            }
            __syncthreads();

            if (wid < 8) {
                // bnlin split unit
                const int ms = wid >> 1, nh = wid & 1;
                const int r0 = ms * 16 + lr;
                const float* whi = sm + WB_OFF + 3 * WSLOT;
                const float* wlo = sm + WB_OFF + 4 * WSLOT;
                #pragma unroll
                for (int step = 0; step < 8; ++step) {
                    int kc = ch * 64 + step * 8 + lk;
                    float x0 = sm[XS_OFF + r0 * XS_LD + kc];
                    float x1 = sm[XS_OFF + (r0 + 8) * XS_LD + kc];
                    float x2 = sm[XS_OFF + r0 * XS_LD + kc + 4];
                    float x3 = sm[XS_OFF + (r0 + 8) * XS_LD + kc + 4];
                    uint32 h0 = cvt_tf32(x0), h1 = cvt_tf32(x1), h2 = cvt_tf32(x2), h3 = cvt_tf32(x3);
                    uint32 l0 = cvt_tf32(x0 - __uint_as_float(h0));
                    uint32 l1 = cvt_tf32(x1 - __uint_as_float(h1));
                    uint32 l2 = cvt_tf32(x2 - __uint_as_float(h2));
                    uint32 l3 = cvt_tf32(x3 - __uint_as_float(h3));
                    int kw = step * 8 + lk;
                    #pragma unroll
                    for (int t = 0; t < 4; ++t) {
                        int n = nh * 32 + t * 8 + lr;
                        uint32 bh0 = __float_as_uint(whi[n * HB_LD + kw]);
                        uint32 bh1 = __float_as_uint(whi[n * HB_LD + kw + 4]);
                        uint32 bl0 = __float_as_uint(wlo[n * HB_LD + kw]);
                        uint32 bl1 = __float_as_uint(wlo[n * HB_LD + kw + 4]);
                        mma_tf32(dB[t], h0, h1, h2, h3, bh0, bh1);
                        mma_tf32(dB[t], h0, h1, h2, h3, bl0, bl1);
                        mma_tf32(dB[t], l0, l1, l2, l3, bh0, bh1);
                    }
                }
            } else {
                // light: A-frag loaded once, shared across 3 matrices
                const int lw = wid - 8;
                const int ms = lw & 3, nh = lw >> 2;
                const int r0 = ms * 16 + lr;
                #pragma unroll
                for (int step = 0; step < 8; ++step) {
                    int kc = ch * 64 + step * 8 + lk;
                    uint32 a0 = cvt_tf32(sm[XS_OFF + r0 * XS_LD + kc]);
                    uint32 a1 = cvt_tf32(sm[XS_OFF + (r0 + 8) * XS_LD + kc]);
                    uint32 a2 = cvt_tf32(sm[XS_OFF + r0 * XS_LD + kc + 4]);
                    uint32 a3 = cvt_tf32(sm[XS_OFF + (r0 + 8) * XS_LD + kc + 4]);
                    int kw = step * 8 + lk;
                    #pragma unroll
                    for (int mat = 0; mat < 3; ++mat) {
                        const float* wt = sm + WB_OFF + mat * WSLOT;
                        #pragma unroll
                        for (int t = 0; t < 4; ++t) {
                            int n = nh * 32 + t * 8 + lr;
                            uint32 b0 = __float_as_uint(wt[n * HB_LD + kw]);
                            uint32 b1 = __float_as_uint(wt[n * HB_LD + kw + 4]);
                            mma_tf32(dL[mat][t], a0, a1, a2, a3, b0, b1);
                        }
                    }
                }
            }
            __syncthreads();
        }

        // epilogue
        if (wid < 8) {
            const int ms = wid >> 1, nh = wid & 1;
            int rb = ms * 16 + lr;
            #pragma unroll
            for (int t = 0; t < 4; ++t) {
                int cb = nh * 32 + t * 8 + lk * 2;
                float b0v = __ldg(&bnlin_b[cb]), b1v = __ldg(&bnlin_b[cb + 1]);
                float2 lo_, hi_;
                lo_.x = tanhf(dB[t][0] + b0v); lo_.y = tanhf(dB[t][1] + b1v);
                hi_.x = tanhf(dB[t][2] + b0v); hi_.y = tanhf(dB[t][3] + b1v);
                *reinterpret_cast<float2*>(sm + HH_OFF + rb * HB_LD + cb)       = lo_;
                *reinterpret_cast<float2*>(sm + HH_OFF + (rb + 8) * HB_LD + cb) = hi_;
            }
        } else {
            const int lw = wid - 8;
            const int ms = lw & 3, nh = lw >> 2;
            int rb = ms * 16 + lr;
            #pragma unroll
            for (int t = 0; t < 4; ++t) {
                int cb = nh * 32 + t * 8 + lk * 2;
                float b0v = __ldg(&gate_b[cb]), b1v = __ldg(&gate_b[cb + 1]);
                float2 lo_, hi_;
                lo_.x = tanhf(dL[0][t][0] + b0v); lo_.y = tanhf(dL[0][t][1] + b1v);
                hi_.x = tanhf(dL[0][t][2] + b0v); hi_.y = tanhf(dL[0][t][3] + b1v);
                *reinterpret_cast<float2*>(sm + MASK_OFF + rb * HB_LD + cb)       = lo_;
                *reinterpret_cast<float2*>(sm + MASK_OFF + (rb + 8) * HB_LD + cb) = hi_;
                lo_.x = dL[1][t][0]; lo_.y = dL[1][t][1];
                hi_.x = dL[1][t][2]; hi_.y = dL[1][t][3];
                *reinterpret_cast<float2*>(sm + A_OFF + rb * HB_LD + cb)       = lo_;
                *reinterpret_cast<float2*>(sm + A_OFF + (rb + 8) * HB_LD + cb) = hi_;
                lo_.x = dL[2][t][0]; lo_.y = dL[2][t][1];
                hi_.x = dL[2][t][2]; hi_.y = dL[2][t][3];
                *reinterpret_cast<float2*>(sm + B_OFF + rb * HB_LD + cb)       = lo_;
                *reinterpret_cast<float2*>(sm + B_OFF + (rb + 8) * HB_LD + cb) = hi_;
            }
        }
    }
    __syncthreads();

    // -------- Phase 2: adjacency logits (fp32 exact) -----------------------
    {
        const int rr = tid >> 3;
        const int jg = tid & 7;
        ull s2[8];
        #pragma unroll
        for (int q = 0; q < 8; ++q) s2[q] = 0ull;
        const float* xa = sm + HH_OFF;
        for (int k = 0; k < HID; k += 4) {
            ulonglong2 a = *reinterpret_cast<const ulonglong2*>(xa + rr * HB_LD + k);
            #pragma unroll
            for (int q = 0; q < 8; ++q) {
                ulonglong2 aj = *reinterpret_cast<const ulonglong2*>(xa + (jg + 8 * q) * HB_LD + k);
                s2[q] = ffma2(a.x, aj.x, s2[q]);
                s2[q] = ffma2(a.y, aj.y, s2[q]);
            }
        }
        float* adj = sm + ADJ_OFF;
        if (rr < CN) {
            #pragma unroll
            for (int q = 0; q < 8; ++q) {
                int j = jg + 8 * q;
                if (j < CN) {
                    float2 v = unpack2(s2[q]);
                    adj[rr * 64 + j] = v.x + v.y;
                }
            }
        }
    }
    __syncthreads();

    // ---------- Phase 3: softmax + top-10 ----------------------------------
    {
        int* tix = reinterpret_cast<int*>(sm);
        for (int r = wid; r < CN; r += 16) {
            const float* arow = sm + ADJ_OFF + r * 64;
            float a0 = arow[lane];
            bool ok1 = (lane + 32) < CN;
            float a1 = ok1 ? arow[lane + 32] : -1e30f;
            float mx = fmaxf(a0, a1);
            #pragma unroll
            for (int o = 16; o; o >>= 1) mx = fmaxf(mx, __shfl_xor_sync(0xffffffffu, mx, o));
            float e0 = expf(a0 - mx);
            float e1 = ok1 ? expf(a1 - mx) : 0.f;
            float s = e0 + e1;
            #pragma unroll
            for (int o = 16; o; o >>= 1) s += __shfl_xor_sync(0xffffffffu, s, o);
            float inv = 1.f / s;
            float p0 = e0 * inv, p1 = e1 * inv;
            float v0 = p0;
            float v1 = ok1 ? p1 : -1.f;
            for (int m = 0; m < TOPK; ++m) {
                float c  = fmaxf(v0, v1);
                float cm = c;
                #pragma unroll
                for (int o = 16; o; o >>= 1) cm = fmaxf(cm, __shfl_xor_sync(0xffffffffu, cm, o));
                unsigned ball = __ballot_sync(0xffffffffu, c == cm);
                int owner = __ffs(ball) - 1;
                if (lane == owner) {
                    if (v0 == cm) {
                        sm[TV_OFF + r * TOPK + m] = p0;
                        tix[TI_OFF + r * TOPK + m] = lane;
                        v0 = -1.f;
                    } else {
                        sm[TV_OFF + r * TOPK + m] = p1;
                        tix[TI_OFF + r * TOPK + m] = lane + 32;
                        v1 = -1.f;
                    }
                }
            }
        }
    }
    __syncthreads();

    // ---------- Phase 4: h1 = relu(adjS @ A + rel_b1 + B) ------------------
    {
        const int r   = tid >> 3;
        const int cg  = tid & 7;
        const int c0a = cg * 4;
        const int c0b = 32 + cg * 4;
        float* hr0 = sm + HH_OFF + r * HB_LD + c0a;
        float* hr1 = sm + HH_OFF + r * HB_LD + c0b;
        if (r < CN) {
            const int* tix = reinterpret_cast<const int*>(sm);
            ull s[4] = {0ull, 0ull, 0ull, 0ull};
            #pragma unroll
            for (int m = 0; m < TOPK; ++m) {
                int   j = tix[TI_OFF + r * TOPK + m];
                ull  vp = pack2(sm[TV_OFF + r * TOPK + m]);
                ulonglong2 pa = *reinterpret_cast<const ulonglong2*>(sm + A_OFF + j * HB_LD + c0a);
                ulonglong2 pb = *reinterpret_cast<const ulonglong2*>(sm + A_OFF + j * HB_LD + c0b);
                s[0] = ffma2(vp, pa.x, s[0]);
                s[1] = ffma2(vp, pa.y, s[1]);
                s[2] = ffma2(vp, pb.x, s[2]);
                s[3] = ffma2(vp, pb.y, s[3]);
            }
            float4 r0 = *reinterpret_cast<const float4*>(sm + B_OFF + r * HB_LD + c0a);
            float4 r1 = *reinterpret_cast<const float4*>(sm + B_OFF + r * HB_LD + c0b);
            float2 v0 = unpack2(s[0]), v1 = unpack2(s[1]);
            float2 v2 = unpack2(s[2]), v3 = unpack2(s[3]);
            float4 t0, t1;
            t0.x = fmaxf(v0.x + __ldg(&rel_b1[c0a + 0]) + r0.x, 0.f);
            t0.y = fmaxf(v0.y + __ldg(&rel_b1[c0a + 1]) + r0.y, 0.f);
            t0.z = fmaxf(v1.x + __ldg(&rel_b1[c0a + 2]) + r0.z, 0.f);
            t0.w = fmaxf(v1.y + __ldg(&rel_b1[c0a + 3]) + r0.w, 0.f);
            t1.x = fmaxf(v2.x + __ldg(&rel_b1[c0b + 0]) + r1.x, 0.f);
            t1.y = fmaxf(v2.y + __ldg(&rel_b1[c0b + 1]) + r1.y, 0.f);
            t1.z = fmaxf(v3.x + __ldg(&rel_b1[c0b + 2]) + r1.z, 0.f);
            t1.w = fmaxf(v3.y + __ldg(&rel_b1[c0b + 3]) + r1.w, 0.f);
            *reinterpret_cast<float4*>(hr0) = t0;
            *reinterpret_cast<float4*>(hr1) = t1;
        } else {
            float4 z = make_float4(0.f, 0.f, 0.f, 0.f);
            *reinterpret_cast<float4*>(hr0) = z;
            *reinterpret_cast<float4*>(hr1) = z;
        }
    }
    __syncthreads();

    // ---------------- Phase 5: six layers ----------------------------------
    for (int L = 0; L < 6; ++L) {
        // stage pre-transposed tf32 mid weights (float4, conflict-free)
        {
            int mr4 = (MIDREL_F >> 2) + L * 1024;
            int mo4 = (MIDROOT_F >> 2) + L * 1024;
            for (int g = tid; g < 1024; g += NT) {
                int n = g >> 4, kq = g & 15;
                int dst = n * 17 + kq;
                wb4[dst]        = wT4[mr4 + g];
                wb4[1088 + dst] = wT4[mo4 + g];
            }
        }
        __syncthreads();

        // GEMM: 16 units = mat(2) x ms(4) x nh(2); warp -> one unit
        {
            const int mat = wid >> 3, ms = (wid >> 1) & 3, nh = wid & 1;
            const int lr = lane >> 2, lk = lane & 3;
            const int r0 = ms * 16 + lr;
            const float* wt = sm + WB_OFF + mat * WSLOT;
            const float* hb = sm + HH_OFF;
            float d[4][4];
            #pragma unroll
            for (int t = 0; t < 4; ++t)
                #pragma unroll
                for (int i = 0; i < 4; ++i) d[t][i] = 0.f;
            #pragma unroll
            for (int step = 0; step < 8; ++step) {
                int kc = step * 8 + lk;
                uint32 a0 = cvt_tf32(hb[r0 * HB_LD + kc]);
                uint32 a1 = cvt_tf32(hb[(r0 + 8) * HB_LD + kc]);
                uint32 a2 = cvt_tf32(hb[r0 * HB_LD + kc + 4]);
                uint32 a3 = cvt_tf32(hb[(r0 + 8) * HB_LD + kc + 4]);
                #pragma unroll
                for (int t = 0; t < 4; ++t) {
                    int n = nh * 32 + t * 8 + lr;
                    uint32 b0 = __float_as_uint(wt[n * HB_LD + kc]);
                    uint32 b1 = __float_as_uint(wt[n * HB_LD + kc + 4]);
                    mma_tf32(d[t], a0, a1, a2, a3, b0, b1);
                }
            }
            float* base = sm + (mat ? B_OFF : A_OFF);
            int rb = ms * 16 + lr;
            #pragma unroll
            for (int t = 0; t < 4; ++t) {
                int cb = nh * 32 + t * 8 + lk * 2;
                float2 lo_, hi_;
                lo_.x = d[t][0]; lo_.y = d[t][1];
                hi_.x = d[t][2]; hi_.y = d[t][3];
                *reinterpret_cast<float2*>(base + rb * HB_LD + cb)       = lo_;
                *reinterpret_cast<float2*>(base + (rb + 8) * HB_LD + cb) = hi_;
            }
        }
        __syncthreads();

        // update: t = relu(adjS @ hr + rel_b_mid[L] + hroot); h+=t / out
        {
            const int r   = tid >> 3;
            const int cg  = tid & 7;
            const int c0a = cg * 4;
            const int c0b = 32 + cg * 4;
            if (r < CN) {
                const int* tix = reinterpret_cast<const int*>(sm);
                const float* relb = rel_b_mid + L * 64;
                ull s[4] = {0ull, 0ull, 0ull, 0ull};
                #pragma unroll
                for (int m = 0; m < TOPK; ++m) {
                    int   j = tix[TI_OFF + r * TOPK + m];
                    ull  vp = pack2(sm[TV_OFF + r * TOPK + m]);
                    ulonglong2 pa = *reinterpret_cast<const ulonglong2*>(sm + A_OFF + j * HB_LD + c0a);
                    ulonglong2 pb = *reinterpret_cast<const ulonglong2*>(sm + A_OFF + j * HB_LD + c0b);
                    s[0] = ffma2(vp, pa.x, s[0]);
                    s[1] = ffma2(vp, pa.y, s[1]);
                    s[2] = ffma2(vp, pb.x, s[2]);
                    s[3] = ffma2(vp, pb.y, s[3]);
                }
                float4 r0 = *reinterpret_cast<const float4*>(sm + B_OFF + r * HB_LD + c0a);
                float4 r1 = *reinterpret_cast<const float4*>(sm + B_OFF + r * HB_LD + c0b);
                float2 v0 = unpack2(s[0]), v1 = unpack2(s[1]);
                float2 v2 = unpack2(s[2]), v3 = unpack2(s[3]);
                float4 t0, t1;
                t0.x = fmaxf(v0.x + __ldg(&relb[c0a + 0]) + r0.x, 0.f);
                t0.y = fmaxf(v0.y + __ldg(&relb[c0a + 1]) + r0.y, 0.f);
                t0.z = fmaxf(v1.x + __ldg(&relb[c0a + 2]) + r0.z, 0.f);
                t0.w = fmaxf(v1.y + __ldg(&relb[c0a + 3]) + r0.w, 0.f);
                t1.x = fmaxf(v2.x + __ldg(&relb[c0b + 0]) + r1.x, 0.f);
                t1.y = fmaxf(v2.y + __ldg(&relb[c0b + 1]) + r1.y, 0.f);
                t1.z = fmaxf(v3.x + __ldg(&relb[c0b + 2]) + r1.z, 0.f);
                t1.w = fmaxf(v3.y + __ldg(&relb[c0b + 3]) + r1.w, 0.f);
                float* h0 = sm + HH_OFF + r * HB_LD + c0a;
                float* h1 = sm + HH_OFF + r * HB_LD + c0b;
                if (L < 5) {
                    float4 ha = *reinterpret_cast<const float4*>(h0);
                    float4 hbv = *reinterpret_cast<const float4*>(h1);
                    ha.x += t0.x; ha.y += t0.y; ha.z += t0.z; ha.w += t0.w;
                    hbv.x += t1.x; hbv.y += t1.y; hbv.z += t1.z; hbv.w += t1.w;
                    *reinterpret_cast<float4*>(h0) = ha;
                    *reinterpret_cast<float4*>(h1) = hbv;
                } else {
                    float4 m0 = *reinterpret_cast<const float4*>(sm + MASK_OFF + r * HB_LD + c0a);
                    float4 m1 = *reinterpret_cast<const float4*>(sm + MASK_OFF + r * HB_LD + c0b);
                    float4 o0, o1;
                    o0.x = t0.x * m0.x; o0.y = t0.y * m0.y; o0.z = t0.z * m0.z; o0.w = t0.w * m0.w;
                    o1.x = t1.x * m1.x; o1.y = t1.y * m1.y; o1.z = t1.z * m1.z; o1.w = t1.w * m1.w;
                    float* og = out + (size_t)b * (CN * HID) + r * HID;
                    *reinterpret_cast<float4*>(og + c0a) = o0;
                    *reinterpret_cast<float4*>(og + c0b) = o1;
                }
            }
        }
        if (L < 5) __syncthreads();
    }
}

extern "C" void kernel_launch(void* const* d_in, const int* in_sizes, int n_in,
                              void* d_out, int out_size) {
    const float* x          = (const float*)d_in[0];
    const float* gate_w     = (const float*)d_in[1];
    const float* gate_b     = (const float*)d_in[2];
    const float* bnlin_w    = (const float*)d_in[3];
    const float* bnlin_b    = (const float*)d_in[4];
    const float* rel_w1     = (const float*)d_in[5];
    const float* rel_b1     = (const float*)d_in[6];
    const float* root_w1    = (const float*)d_in[7];
    const float* rel_w_mid  = (const float*)d_in[8];
    const float* rel_b_mid  = (const float*)d_in[9];
    const float* root_w_mid = (const float*)d_in[10];
    float* out = (float*)d_out;

    (void)in_sizes; (void)n_in; (void)out_size;

    prep_weights<<<96, 256>>>(gate_w, bnlin_w, rel_w1, root_w1, rel_w_mid, root_w_mid);

    const int smem_bytes = SMEM_FLOATS * 4;   // 228192
    cudaFuncSetAttribute(residual_graph_kernel,
                         cudaFuncAttributeMaxDynamicSharedMemorySize, smem_bytes);
    residual_graph_kernel<<<NB, NT, smem_bytes>>>(
        x, gate_b, bnlin_b, rel_b1, rel_b_mid, out);
}

// round 13
// speedup vs baseline: 3.4085x; 1.0618x over previous
#include <cuda_runtime.h>

// Problem constants
static constexpr int NB   = 4096;
static constexpr int CN   = 62;
static constexpr int FIN  = 256;
static constexpr int HID  = 64;
static constexpr int TOPK = 10;
static constexpr int NT   = 512;

// SMEM strides (floats)
static constexpr int XS_LD = 260;
static constexpr int HB_LD = 68;

// SMEM layout (floats)
static constexpr int XS_OFF   = 0;                  // 16640 (x; ADJ overlays later)
static constexpr int ADJ_OFF  = 0;
static constexpr int WB_OFF   = 16640;              // 21760: phase1 = 5 slots; phase5 = 2 x 2-slot double buffer
static constexpr int WSLOT    = 4352;
static constexpr int MASK_OFF = WB_OFF + 21760;     // 38400
static constexpr int HH_OFF   = MASK_OFF + 4352;    // 42752 (xa then h)
static constexpr int A_OFF    = HH_OFF + 4352;      // 47104
static constexpr int B_OFF    = A_OFF + 4352;       // 51456
static constexpr int TV_OFF   = B_OFF + 4352;       // 55808
static constexpr int TI_OFF   = TV_OFF + 620;       // 56428
static constexpr int SMEM_FLOATS = TI_OFF + 620;    // 57048 fl = 228192 B

// Pre-transposed tf32 weights in device global
static constexpr int W1SLOT_F  = 16384;
static constexpr int MIDREL_F  = 5 * W1SLOT_F;          // 81920
static constexpr int MIDROOT_F = MIDREL_F + 6 * 4096;   // 106496
static constexpr int WT_FLOATS = MIDROOT_F + 6 * 4096;  // 131072
__device__ float g_wT[WT_FLOATS];

typedef unsigned long long ull;
typedef unsigned int uint32;

__device__ __forceinline__ ull ffma2(ull a, ull b, ull c) {
    ull d; asm("fma.rn.f32x2 %0, %1, %2, %3;" : "=l"(d) : "l"(a), "l"(b), "l"(c)); return d;
}
__device__ __forceinline__ ull pack2(float x) {
    ull r; asm("mov.b64 %0, {%1, %1};" : "=l"(r) : "f"(x)); return r;
}
__device__ __forceinline__ float2 unpack2(ull v) {
    float2 r; asm("mov.b64 {%0, %1}, %2;" : "=f"(r.x), "=f"(r.y) : "l"(v)); return r;
}
__device__ __forceinline__ uint32 cvt_tf32(float x) {
    uint32 r; asm("cvt.rna.tf32.f32 %0, %1;" : "=r"(r) : "f"(x)); return r;
}
__device__ __forceinline__ void mma_tf32(float d[4], uint32 a0, uint32 a1, uint32 a2, uint32 a3,
                                         uint32 b0, uint32 b1) {
    asm volatile(
        "mma.sync.aligned.m16n8k8.row.col.f32.tf32.tf32.f32 "
        "{%0,%1,%2,%3}, {%4,%5,%6,%7}, {%8,%9}, {%0,%1,%2,%3};"
        : "+f"(d[0]), "+f"(d[1]), "+f"(d[2]), "+f"(d[3])
        : "r"(a0), "r"(a1), "r"(a2), "r"(a3), "r"(b0), "r"(b1));
}

// ---- prep kernel: transpose + tf32-convert all weights once per launch ----
__global__ void prep_weights(
    const float* __restrict__ gate_w,  const float* __restrict__ bnlin_w,
    const float* __restrict__ rel_w1,  const float* __restrict__ root_w1,
    const float* __restrict__ rel_w_mid, const float* __restrict__ root_w_mid)
{
    int i = blockIdx.x * blockDim.x + threadIdx.x;
    if (i < 16384) {
        int n = i >> 8, k = i & 255;
        int src = k * 64 + n;
        int dst = n * 256 + k;
        g_wT[0 * W1SLOT_F + dst] = __uint_as_float(cvt_tf32(__ldg(&gate_w[src])));
        g_wT[1 * W1SLOT_F + dst] = __uint_as_float(cvt_tf32(__ldg(&rel_w1[src])));
        g_wT[2 * W1SLOT_F + dst] = __uint_as_float(cvt_tf32(__ldg(&root_w1[src])));
        float bn = __ldg(&bnlin_w[src]);
        uint32 hi = cvt_tf32(bn);
        g_wT[3 * W1SLOT_F + dst] = __uint_as_float(hi);
        g_wT[4 * W1SLOT_F + dst] = __uint_as_float(cvt_tf32(bn - __uint_as_float(hi)));
    }
    if (i < 24576) {
        int L = i >> 12, idx = i & 4095;
        int n = idx >> 6, k = idx & 63;
        int src = L * 4096 + k * 64 + n;
        int dst = L * 4096 + n * 64 + k;
        g_wT[MIDREL_F + dst]  = __uint_as_float(cvt_tf32(__ldg(&rel_w_mid[src])));
        g_wT[MIDROOT_F + dst] = __uint_as_float(cvt_tf32(__ldg(&root_w_mid[src])));
    }
}

__global__ __launch_bounds__(NT, 1) void residual_graph_kernel(
    const float* __restrict__ x,
    const float* __restrict__ gate_b,
    const float* __restrict__ bnlin_b,
    const float* __restrict__ rel_b1,
    const float* __restrict__ rel_b_mid,
    float* __restrict__ out)
{
    extern __shared__ float sm[];
    const int b    = blockIdx.x;
    const int tid  = threadIdx.x;
    const int lane = tid & 31;
    const int wid  = tid >> 5;

    const float4* wT4 = reinterpret_cast<const float4*>(g_wT);
    float4* wb4 = reinterpret_cast<float4*>(sm + WB_OFF);

    // ---------------- Phase 0: load x tile ----------------
    {
        const float4* xg  = reinterpret_cast<const float4*>(x + (size_t)b * (CN * FIN));
        float4*       xs4 = reinterpret_cast<float4*>(sm + XS_OFF);
        for (int i = tid; i < CN * 64; i += NT) {
            int r = i >> 6, q = i & 63;
            xs4[r * (XS_LD / 4) + q] = xg[i];
        }
        float4 z = make_float4(0.f, 0.f, 0.f, 0.f);
        if (tid < 2 * 64) {
            int r = 62 + (tid >> 6), q = tid & 63;
            xs4[r * (XS_LD / 4) + q] = z;
        }
    }
    __syncthreads();

    // ---- Phase 1: four [62,256]x[256,64] GEMMs via mma.sync tf32 ----------
    {
        const int lr = lane >> 2;
        const int lk = lane & 3;
        float dB[4][4];
        float dL[3][4][4];
        #pragma unroll
        for (int t = 0; t < 4; ++t)
            #pragma unroll
            for (int i = 0; i < 4; ++i) dB[t][i] = 0.f;
        #pragma unroll
        for (int u = 0; u < 3; ++u)
            #pragma unroll
            for (int t = 0; t < 4; ++t)
                #pragma unroll
                for (int i = 0; i < 4; ++i) dL[u][t][i] = 0.f;

        for (int ch = 0; ch < 4; ++ch) {
            // stage 5 pre-transposed tf32 weight chunks, float4, conflict-free
            for (int g = tid; g < 1024; g += NT) {
                int n = g >> 4, kq = g & 15;
                int srcb = n * 64 + ch * 16 + kq;
                int dst  = n * 17 + kq;
                wb4[0 * 1088 + dst] = wT4[0 * 4096 + srcb];
                wb4[1 * 1088 + dst] = wT4[1 * 4096 + srcb];
                wb4[2 * 1088 + dst] = wT4[2 * 4096 + srcb];
                wb4[3 * 1088 + dst] = wT4[3 * 4096 + srcb];
                wb4[4 * 1088 + dst] = wT4[4 * 4096 + srcb];
            }
            __syncthreads();

            if (wid < 8) {
                // bnlin split unit
                const int ms = wid >> 1, nh = wid & 1;
                const int r0 = ms * 16 + lr;
                const float* whi = sm + WB_OFF + 3 * WSLOT;
                const float* wlo = sm + WB_OFF + 4 * WSLOT;
                #pragma unroll
                for (int step = 0; step < 8; ++step) {
                    int kc = ch * 64 + step * 8 + lk;
                    float x0 = sm[XS_OFF + r0 * XS_LD + kc];
                    float x1 = sm[XS_OFF + (r0 + 8) * XS_LD + kc];
                    float x2 = sm[XS_OFF + r0 * XS_LD + kc + 4];
                    float x3 = sm[XS_OFF + (r0 + 8) * XS_LD + kc + 4];
                    uint32 h0 = cvt_tf32(x0), h1 = cvt_tf32(x1), h2 = cvt_tf32(x2), h3 = cvt_tf32(x3);
                    uint32 l0 = cvt_tf32(x0 - __uint_as_float(h0));
                    uint32 l1 = cvt_tf32(x1 - __uint_as_float(h1));
                    uint32 l2 = cvt_tf32(x2 - __uint_as_float(h2));
                    uint32 l3 = cvt_tf32(x3 - __uint_as_float(h3));
                    int kw = step * 8 + lk;
                    #pragma unroll
                    for (int t = 0; t < 4; ++t) {
                        int n = nh * 32 + t * 8 + lr;
                        uint32 bh0 = __float_as_uint(whi[n * HB_LD + kw]);
                        uint32 bh1 = __float_as_uint(whi[n * HB_LD + kw + 4]);
                        uint32 bl0 = __float_as_uint(wlo[n * HB_LD + kw]);
                        uint32 bl1 = __float_as_uint(wlo[n * HB_LD + kw + 4]);
                        mma_tf32(dB[t], h0, h1, h2, h3, bh0, bh1);
                        mma_tf32(dB[t], h0, h1, h2, h3, bl0, bl1);
                        mma_tf32(dB[t], l0, l1, l2, l3, bh0, bh1);
                    }
                }
            } else {
                // light: A-frag loaded once, shared across 3 matrices
                const int lw = wid - 8;
                const int ms = lw & 3, nh = lw >> 2;
                const int r0 = ms * 16 + lr;
                #pragma unroll
                for (int step = 0; step < 8; ++step) {
                    int kc = ch * 64 + step * 8 + lk;
                    uint32 a0 = cvt_tf32(sm[XS_OFF + r0 * XS_LD + kc]);
                    uint32 a1 = cvt_tf32(sm[XS_OFF + (r0 + 8) * XS_LD + kc]);
                    uint32 a2 = cvt_tf32(sm[XS_OFF + r0 * XS_LD + kc + 4]);
                    uint32 a3 = cvt_tf32(sm[XS_OFF + (r0 + 8) * XS_LD + kc + 4]);
                    int kw = step * 8 + lk;
                    #pragma unroll
                    for (int mat = 0; mat < 3; ++mat) {
                        const float* wt = sm + WB_OFF + mat * WSLOT;
                        #pragma unroll
                        for (int t = 0; t < 4; ++t) {
                            int n = nh * 32 + t * 8 + lr;
                            uint32 b0 = __float_as_uint(wt[n * HB_LD + kw]);
                            uint32 b1 = __float_as_uint(wt[n * HB_LD + kw + 4]);
                            mma_tf32(dL[mat][t], a0, a1, a2, a3, b0, b1);
                        }
                    }
                }
            }
            __syncthreads();
        }

        // epilogue
        if (wid < 8) {
            const int ms = wid >> 1, nh = wid & 1;
            int rb = ms * 16 + lr;
            #pragma unroll
            for (int t = 0; t < 4; ++t) {
                int cb = nh * 32 + t * 8 + lk * 2;
                float b0v = __ldg(&bnlin_b[cb]), b1v = __ldg(&bnlin_b[cb + 1]);
                float2 lo_, hi_;
                lo_.x = tanhf(dB[t][0] + b0v); lo_.y = tanhf(dB[t][1] + b1v);
                hi_.x = tanhf(dB[t][2] + b0v); hi_.y = tanhf(dB[t][3] + b1v);
                *reinterpret_cast<float2*>(sm + HH_OFF + rb * HB_LD + cb)       = lo_;
                *reinterpret_cast<float2*>(sm + HH_OFF + (rb + 8) * HB_LD + cb) = hi_;
            }
        } else {
            const int lw = wid - 8;
            const int ms = lw & 3, nh = lw >> 2;
            int rb = ms * 16 + lr;
            #pragma unroll
            for (int t = 0; t < 4; ++t) {
                int cb = nh * 32 + t * 8 + lk * 2;
                float b0v = __ldg(&gate_b[cb]), b1v = __ldg(&gate_b[cb + 1]);
                float2 lo_, hi_;
                lo_.x = tanhf(dL[0][t][0] + b0v); lo_.y = tanhf(dL[0][t][1] + b1v);
                hi_.x = tanhf(dL[0][t][2] + b0v); hi_.y = tanhf(dL[0][t][3] + b1v);
                *reinterpret_cast<float2*>(sm + MASK_OFF + rb * HB_LD + cb)       = lo_;
                *reinterpret_cast<float2*>(sm + MASK_OFF + (rb + 8) * HB_LD + cb) = hi_;
                lo_.x = dL[1][t][0]; lo_.y = dL[1][t][1];
                hi_.x = dL[1][t][2]; hi_.y = dL[1][t][3];
                *reinterpret_cast<float2*>(sm + A_OFF + rb * HB_LD + cb)       = lo_;
                *reinterpret_cast<float2*>(sm + A_OFF + (rb + 8) * HB_LD + cb) = hi_;
                lo_.x = dL[2][t][0]; lo_.y = dL[2][t][1];
                hi_.x = dL[2][t][2]; hi_.y = dL[2][t][3];
                *reinterpret_cast<float2*>(sm + B_OFF + rb * HB_LD + cb)       = lo_;
                *reinterpret_cast<float2*>(sm + B_OFF + (rb + 8) * HB_LD + cb) = hi_;
            }
        }
    }
    __syncthreads();

    // ---- Stage layer-0 mid weights into WB buf0 (hidden behind ph 2-4) ----
    {
        int mr4 = (MIDREL_F >> 2);
        int mo4 = (MIDROOT_F >> 2);
        for (int g = tid; g < 1024; g += NT) {
            int n = g >> 4, kq = g & 15;
            int dst = n * 17 + kq;
            wb4[dst]        = wT4[mr4 + g];
            wb4[1088 + dst] = wT4[mo4 + g];
        }
    }

    // -------- Phase 2: adjacency logits via Markidis tf32 mma (~2^-22) -----
    {
        const int lr = lane >> 2, lk = lane & 3;
        const int ms = wid & 3, nq = wid >> 2;   // M-tile 16, N-tile 16
        const int r0 = ms * 16 + lr;
        const float* xa = sm + HH_OFF;
        float d[2][4];
        #pragma unroll
        for (int t = 0; t < 2; ++t)
            #pragma unroll
            for (int i = 0; i < 4; ++i) d[t][i] = 0.f;
        #pragma unroll
        for (int step = 0; step < 8; ++step) {
            int kc = step * 8 + lk;
            float a0 = xa[r0 * HB_LD + kc];
            float a1 = xa[(r0 + 8) * HB_LD + kc];
            float a2 = xa[r0 * HB_LD + kc + 4];
            float a3 = xa[(r0 + 8) * HB_LD + kc + 4];
            uint32 ah0 = cvt_tf32(a0), ah1 = cvt_tf32(a1), ah2 = cvt_tf32(a2), ah3 = cvt_tf32(a3);
            uint32 al0 = cvt_tf32(a0 - __uint_as_float(ah0));
            uint32 al1 = cvt_tf32(a1 - __uint_as_float(ah1));
            uint32 al2 = cvt_tf32(a2 - __uint_as_float(ah2));
            uint32 al3 = cvt_tf32(a3 - __uint_as_float(ah3));
            #pragma unroll
            for (int t = 0; t < 2; ++t) {
                int n = nq * 16 + t * 8 + lr;
                float b0 = xa[n * HB_LD + kc];
                float b1 = xa[n * HB_LD + kc + 4];
                uint32 bh0 = cvt_tf32(b0), bh1 = cvt_tf32(b1);
                uint32 bl0 = cvt_tf32(b0 - __uint_as_float(bh0));
                uint32 bl1 = cvt_tf32(b1 - __uint_as_float(bh1));
                mma_tf32(d[t], ah0, ah1, ah2, ah3, bh0, bh1);
                mma_tf32(d[t], ah0, ah1, ah2, ah3, bl0, bl1);
                mma_tf32(d[t], al0, al1, al2, al3, bh0, bh1);
            }
        }
        float* adj = sm + ADJ_OFF;
        #pragma unroll
        for (int t = 0; t < 2; ++t) {
            int cb = nq * 16 + t * 8 + lk * 2;
            bool c0ok = cb < CN, c1ok = (cb + 1) < CN;
            if (r0 < CN) {
                if (c0ok) adj[r0 * 64 + cb]     = d[t][0];
                if (c1ok) adj[r0 * 64 + cb + 1] = d[t][1];
            }
            if (r0 + 8 < CN) {
                if (c0ok) adj[(r0 + 8) * 64 + cb]     = d[t][2];
                if (c1ok) adj[(r0 + 8) * 64 + cb + 1] = d[t][3];
            }
        }
    }
    __syncthreads();

    // ---------- Phase 3: softmax + top-10 ----------------------------------
    {
        int* tix = reinterpret_cast<int*>(sm);
        for (int r = wid; r < CN; r += 16) {
            const float* arow = sm + ADJ_OFF + r * 64;
            float a0 = arow[lane];
            bool ok1 = (lane + 32) < CN;
            float a1 = ok1 ? arow[lane + 32] : -1e30f;
            float mx = fmaxf(a0, a1);
            #pragma unroll
            for (int o = 16; o; o >>= 1) mx = fmaxf(mx, __shfl_xor_sync(0xffffffffu, mx, o));
            float e0 = expf(a0 - mx);
            float e1 = ok1 ? expf(a1 - mx) : 0.f;
            float s = e0 + e1;
            #pragma unroll
            for (int o = 16; o; o >>= 1) s += __shfl_xor_sync(0xffffffffu, s, o);
            float inv = 1.f / s;
            float p0 = e0 * inv, p1 = e1 * inv;
            float v0 = p0;
            float v1 = ok1 ? p1 : -1.f;
            for (int m = 0; m < TOPK; ++m) {
                float c  = fmaxf(v0, v1);
                float cm = c;
                #pragma unroll
                for (int o = 16; o; o >>= 1) cm = fmaxf(cm, __shfl_xor_sync(0xffffffffu, cm, o));
                unsigned ball = __ballot_sync(0xffffffffu, c == cm);
                int owner = __ffs(ball) - 1;
                if (lane == owner) {
                    if (v0 == cm) {
                        sm[TV_OFF + r * TOPK + m] = p0;
                        tix[TI_OFF + r * TOPK + m] = lane;
                        v0 = -1.f;
                    } else {
                        sm[TV_OFF + r * TOPK + m] = p1;
                        tix[TI_OFF + r * TOPK + m] = lane + 32;
                        v1 = -1.f;
                    }
                }
            }
        }
    }
    __syncthreads();

    // ---------- Phase 4: h1 = relu(adjS @ A + rel_b1 + B) ------------------
    {
        const int r   = tid >> 3;
        const int cg  = tid & 7;
        const int c0a = cg * 4;
        const int c0b = 32 + cg * 4;
        float* hr0 = sm + HH_OFF + r * HB_LD + c0a;
        float* hr1 = sm + HH_OFF + r * HB_LD + c0b;
        if (r < CN) {
            const int* tix = reinterpret_cast<const int*>(sm);
            ull s[4] = {0ull, 0ull, 0ull, 0ull};
            #pragma unroll
            for (int m = 0; m < TOPK; ++m) {
                int   j = tix[TI_OFF + r * TOPK + m];
                ull  vp = pack2(sm[TV_OFF + r * TOPK + m]);
                ulonglong2 pa = *reinterpret_cast<const ulonglong2*>(sm + A_OFF + j * HB_LD + c0a);
                ulonglong2 pb = *reinterpret_cast<const ulonglong2*>(sm + A_OFF + j * HB_LD + c0b);
                s[0] = ffma2(vp, pa.x, s[0]);
                s[1] = ffma2(vp, pa.y, s[1]);
                s[2] = ffma2(vp, pb.x, s[2]);
                s[3] = ffma2(vp, pb.y, s[3]);
            }
            float4 r0 = *reinterpret_cast<const float4*>(sm + B_OFF + r * HB_LD + c0a);
            float4 r1 = *reinterpret_cast<const float4*>(sm + B_OFF + r * HB_LD + c0b);
            float2 v0 = unpack2(s[0]), v1 = unpack2(s[1]);
            float2 v2 = unpack2(s[2]), v3 = unpack2(s[3]);
            float4 t0, t1;
            t0.x = fmaxf(v0.x + __ldg(&rel_b1[c0a + 0]) + r0.x, 0.f);
            t0.y = fmaxf(v0.y + __ldg(&rel_b1[c0a + 1]) + r0.y, 0.f);
            t0.z = fmaxf(v1.x + __ldg(&rel_b1[c0a + 2]) + r0.z, 0.f);
            t0.w = fmaxf(v1.y + __ldg(&rel_b1[c0a + 3]) + r0.w, 0.f);
            t1.x = fmaxf(v2.x + __ldg(&rel_b1[c0b + 0]) + r1.x, 0.f);
            t1.y = fmaxf(v2.y + __ldg(&rel_b1[c0b + 1]) + r1.y, 0.f);
            t1.z = fmaxf(v3.x + __ldg(&rel_b1[c0b + 2]) + r1.z, 0.f);
            t1.w = fmaxf(v3.y + __ldg(&rel_b1[c0b + 3]) + r1.w, 0.f);
            *reinterpret_cast<float4*>(hr0) = t0;
            *reinterpret_cast<float4*>(hr1) = t1;
        } else {
            float4 z = make_float4(0.f, 0.f, 0.f, 0.f);
            *reinterpret_cast<float4*>(hr0) = z;
            *reinterpret_cast<float4*>(hr1) = z;
        }
    }
    __syncthreads();

    // ---------------- Phase 5: six layers (double-buffered staging) --------
    for (int L = 0; L < 6; ++L) {
        // GEMM from buffer L&1: 16 units = mat(2) x ms(4) x nh(2)
        {
            const int mat = wid >> 3, ms = (wid >> 1) & 3, nh = wid & 1;
            const int lr = lane >> 2, lk = lane & 3;
            const int r0 = ms * 16 + lr;
            const float* wt = sm + WB_OFF + (L & 1) * 8704 + mat * WSLOT;
            const float* hb = sm + HH_OFF;
            float d[4][4];
            #pragma unroll
            for (int t = 0; t < 4; ++t)
                #pragma unroll
                for (int i = 0; i < 4; ++i) d[t][i] = 0.f;
            #pragma unroll
            for (int step = 0; step < 8; ++step) {
                int kc = step * 8 + lk;
                uint32 a0 = cvt_tf32(hb[r0 * HB_LD + kc]);
                uint32 a1 = cvt_tf32(hb[(r0 + 8) * HB_LD + kc]);
                uint32 a2 = cvt_tf32(hb[r0 * HB_LD + kc + 4]);
                uint32 a3 = cvt_tf32(hb[(r0 + 8) * HB_LD + kc + 4]);
                #pragma unroll
                for (int t = 0; t < 4; ++t) {
                    int n = nh * 32 + t * 8 + lr;
                    uint32 b0 = __float_as_uint(wt[n * HB_LD + kc]);
                    uint32 b1 = __float_as_uint(wt[n * HB_LD + kc + 4]);
                    mma_tf32(d[t], a0, a1, a2, a3, b0, b1);
                }
            }
            float* base = sm + (mat ? B_OFF : A_OFF);
            int rb = ms * 16 + lr;
            #pragma unroll
            for (int t = 0; t < 4; ++t) {
                int cb = nh * 32 + t * 8 + lk * 2;
                float2 lo_, hi_;
                lo_.x = d[t][0]; lo_.y = d[t][1];
                hi_.x = d[t][2]; hi_.y = d[t][3];
                *reinterpret_cast<float2*>(base + rb * HB_LD + cb)       = lo_;
                *reinterpret_cast<float2*>(base + (rb + 8) * HB_LD + cb) = hi_;
            }
        }
        __syncthreads();

        // stage L+1 into the other buffer (overlapped with update)
        if (L < 5) {
            int mr4 = (MIDREL_F >> 2) + (L + 1) * 1024;
            int mo4 = (MIDROOT_F >> 2) + (L + 1) * 1024;
            float4* dstb = wb4 + ((L + 1) & 1) * 2176;
            for (int g = tid; g < 1024; g += NT) {
                int n = g >> 4, kq = g & 15;
                int dst = n * 17 + kq;
                dstb[dst]        = wT4[mr4 + g];
                dstb[1088 + dst] = wT4[mo4 + g];
            }
        }

        // update: t = relu(adjS @ hr + rel_b_mid[L] + hroot); h+=t / out
        {
            const int r   = tid >> 3;
            const int cg  = tid & 7;
            const int c0a = cg * 4;
            const int c0b = 32 + cg * 4;
            if (r < CN) {
                const int* tix = reinterpret_cast<const int*>(sm);
                const float* relb = rel_b_mid + L * 64;
                ull s[4] = {0ull, 0ull, 0ull, 0ull};
                #pragma unroll
                for (int m = 0; m < TOPK; ++m) {
                    int   j = tix[TI_OFF + r * TOPK + m];
                    ull  vp = pack2(sm[TV_OFF + r * TOPK + m]);
                    ulonglong2 pa = *reinterpret_cast<const ulonglong2*>(sm + A_OFF + j * HB_LD + c0a);
                    ulonglong2 pb = *reinterpret_cast<const ulonglong2*>(sm + A_OFF + j * HB_LD + c0b);
                    s[0] = ffma2(vp, pa.x, s[0]);
                    s[1] = ffma2(vp, pa.y, s[1]);
                    s[2] = ffma2(vp, pb.x, s[2]);
                    s[3] = ffma2(vp, pb.y, s[3]);
                }
                float4 r0 = *reinterpret_cast<const float4*>(sm + B_OFF + r * HB_LD + c0a);
                float4 r1 = *reinterpret_cast<const float4*>(sm + B_OFF + r * HB_LD + c0b);
                float2 v0 = unpack2(s[0]), v1 = unpack2(s[1]);
                float2 v2 = unpack2(s[2]), v3 = unpack2(s[3]);
                float4 t0, t1;
                t0.x = fmaxf(v0.x + __ldg(&relb[c0a + 0]) + r0.x, 0.f);
                t0.y = fmaxf(v0.y + __ldg(&relb[c0a + 1]) + r0.y, 0.f);
                t0.z = fmaxf(v1.x + __ldg(&relb[c0a + 2]) + r0.z, 0.f);
                t0.w = fmaxf(v1.y + __ldg(&relb[c0a + 3]) + r0.w, 0.f);
                t1.x = fmaxf(v2.x + __ldg(&relb[c0b + 0]) + r1.x, 0.f);
                t1.y = fmaxf(v2.y + __ldg(&relb[c0b + 1]) + r1.y, 0.f);
                t1.z = fmaxf(v3.x + __ldg(&relb[c0b + 2]) + r1.z, 0.f);
                t1.w = fmaxf(v3.y + __ldg(&relb[c0b + 3]) + r1.w, 0.f);
                float* h0 = sm + HH_OFF + r * HB_LD + c0a;
                float* h1 = sm + HH_OFF + r * HB_LD + c0b;
                if (L < 5) {
                    float4 ha = *reinterpret_cast<const float4*>(h0);
                    float4 hbv = *reinterpret_cast<const float4*>(h1);
                    ha.x += t0.x; ha.y += t0.y; ha.z += t0.z; ha.w += t0.w;
                    hbv.x += t1.x; hbv.y += t1.y; hbv.z += t1.z; hbv.w += t1.w;
                    *reinterpret_cast<float4*>(h0) = ha;
                    *reinterpret_cast<float4*>(h1) = hbv;
                } else {
                    float4 m0 = *reinterpret_cast<const float4*>(sm + MASK_OFF + r * HB_LD + c0a);
                    float4 m1 = *reinterpret_cast<const float4*>(sm + MASK_OFF + r * HB_LD + c0b);
                    float4 o0, o1;
                    o0.x = t0.x * m0.x; o0.y = t0.y * m0.y; o0.z = t0.z * m0.z; o0.w = t0.w * m0.w;
                    o1.x = t1.x * m1.x; o1.y = t1.y * m1.y; o1.z = t1.z * m1.z; o1.w = t1.w * m1.w;
                    float* og = out + (size_t)b * (CN * HID) + r * HID;
                    *reinterpret_cast<float4*>(og + c0a) = o0;
                    *reinterpret_cast<float4*>(og + c0b) = o1;
                }
            }
        }
        if (L < 5) __syncthreads();
    }
}

extern "C" void kernel_launch(void* const* d_in, const int* in_sizes, int n_in,
                              void* d_out, int out_size) {
    const float* x          = (const float*)d_in[0];
    const float* gate_w     = (const float*)d_in[1];
    const float* gate_b     = (const float*)d_in[2];
    const float* bnlin_w    = (const float*)d_in[3];
    const float* bnlin_b    = (const float*)d_in[4];
    const float* rel_w1     = (const float*)d_in[5];
    const float* rel_b1     = (const float*)d_in[6];
    const float* root_w1    = (const float*)d_in[7];
    const float* rel_w_mid  = (const float*)d_in[8];
    const float* rel_b_mid  = (const float*)d_in[9];
    const float* root_w_mid = (const float*)d_in[10];
    float* out = (float*)d_out;

    (void)in_sizes; (void)n_in; (void)out_size;

    prep_weights<<<96, 256>>>(gate_w, bnlin_w, rel_w1, root_w1, rel_w_mid, root_w_mid);

    const int smem_bytes = SMEM_FLOATS * 4;   // 228192
    cudaFuncSetAttribute(residual_graph_kernel,
                         cudaFuncAttributeMaxDynamicSharedMemorySize, smem_bytes);
    residual_graph_kernel<<<NB, NT, smem_bytes>>>(
        x, gate_b, bnlin_b, rel_b1, rel_b_mid, out);
}